// round 1
// baseline (speedup 1.0000x reference)
#include <cuda_runtime.h>
#include <cmath>

// ---------------------------------------------------------------------------
// MaskedAttention: qkv = x @ W^T + b ; q,k,v split ; scores = qk^T/32 ;
// w = softmax(scores) ; out = w @ v.  Outputs: [out (B*S*D) | w (B*S*S)].
// B=4, S=2048, D=1024.
// ---------------------------------------------------------------------------

#define BATCH 4
#define SEQ   2048
#define DIM   1024
#define TDIM  3072              // 3*D
#define ROWS  (BATCH * SEQ)     // 8192

// scratch for qkv projection result: [8192, 3072] row-major
__device__ float g_qkv[(long)ROWS * TDIM];

#define BM 128
#define BN 128
#define BK 16
#define TM 8
#define TN 8
#define NTHREADS 256

// Generic tiled SGEMM.
// TRANSB=true : C[m,n] = scale * sum_k A[m,k]*B[n,k]  (+ bias[n])
// TRANSB=false: C[m,n] = scale * sum_k A[m,k]*B[k,n]  (+ bias[n])
// Batched via blockIdx.z with element strides.
template <bool TRANSB, bool BIAS>
__global__ __launch_bounds__(NTHREADS) void sgemm_kernel(
    const float* __restrict__ Abase, const float* __restrict__ Bbase,
    const float* __restrict__ bias, float* __restrict__ Cbase,
    int K, int lda, int ldb, int ldc,
    long strideA, long strideB, long strideC, float scale)
{
    __shared__ float As[BK][BM];
    __shared__ float Bs[BK][BN];

    const float* A = Abase + (long)blockIdx.z * strideA;
    const float* B = Bbase + (long)blockIdx.z * strideB;
    float*       C = Cbase + (long)blockIdx.z * strideC;

    const int tid = threadIdx.x;
    const int tx = tid & 15;        // 0..15  -> N direction
    const int ty = tid >> 4;        // 0..15  -> M direction
    const int bm = blockIdx.y * BM;
    const int bn = blockIdx.x * BN;

    float acc[TM][TN];
#pragma unroll
    for (int i = 0; i < TM; i++)
#pragma unroll
        for (int j = 0; j < TN; j++) acc[i][j] = 0.0f;

    float ra[TM], rb[TN];

    for (int k0 = 0; k0 < K; k0 += BK) {
        // ---- load A tile (BM x BK), row-major, store transposed As[k][m]
        {
            const int r  = tid >> 2;           // 0..63
            const int c4 = (tid & 3) << 2;     // 0,4,8,12
#pragma unroll
            for (int i = 0; i < 2; i++) {
                const int row = r + i * 64;
                float4 v = *reinterpret_cast<const float4*>(
                    &A[(long)(bm + row) * lda + k0 + c4]);
                As[c4 + 0][row] = v.x;
                As[c4 + 1][row] = v.y;
                As[c4 + 2][row] = v.z;
                As[c4 + 3][row] = v.w;
            }
        }
        // ---- load B tile
        if (TRANSB) {
            // B is [N,K] row-major -> Bs[k][n]
            const int r  = tid >> 2;
            const int c4 = (tid & 3) << 2;
#pragma unroll
            for (int i = 0; i < 2; i++) {
                const int row = r + i * 64;    // n index
                float4 v = *reinterpret_cast<const float4*>(
                    &B[(long)(bn + row) * ldb + k0 + c4]);
                Bs[c4 + 0][row] = v.x;
                Bs[c4 + 1][row] = v.y;
                Bs[c4 + 2][row] = v.z;
                Bs[c4 + 3][row] = v.w;
            }
        } else {
            // B is [K,N] row-major -> Bs[k][n], coalesced float4
            const int n4 = (tid & 31) << 2;    // 0..124*? -> 0..124 step 4
            const int kr = tid >> 5;           // 0..7
#pragma unroll
            for (int i = 0; i < 2; i++) {
                const int kk = kr + i * 8;
                float4 v = *reinterpret_cast<const float4*>(
                    &B[(long)(k0 + kk) * ldb + bn + n4]);
                *reinterpret_cast<float4*>(&Bs[kk][n4]) = v;
            }
        }
        __syncthreads();

#pragma unroll
        for (int kk = 0; kk < BK; kk++) {
#pragma unroll
            for (int i = 0; i < TM; i += 4)
                *reinterpret_cast<float4*>(&ra[i]) =
                    *reinterpret_cast<const float4*>(&As[kk][ty * TM + i]);
#pragma unroll
            for (int j = 0; j < TN; j += 4)
                *reinterpret_cast<float4*>(&rb[j]) =
                    *reinterpret_cast<const float4*>(&Bs[kk][tx * TN + j]);
#pragma unroll
            for (int i = 0; i < TM; i++)
#pragma unroll
                for (int j = 0; j < TN; j++)
                    acc[i][j] = fmaf(ra[i], rb[j], acc[i][j]);
        }
        __syncthreads();
    }

    // ---- epilogue
#pragma unroll
    for (int i = 0; i < TM; i++) {
        const int row = bm + ty * TM + i;
#pragma unroll
        for (int j = 0; j < TN; j += 4) {
            const int col = bn + tx * TN + j;
            float4 v;
            v.x = acc[i][j + 0] * scale;
            v.y = acc[i][j + 1] * scale;
            v.z = acc[i][j + 2] * scale;
            v.w = acc[i][j + 3] * scale;
            if (BIAS) {
                float4 bv = *reinterpret_cast<const float4*>(&bias[col]);
                v.x += bv.x; v.y += bv.y; v.z += bv.z; v.w += bv.w;
            }
            *reinterpret_cast<float4*>(&C[(long)row * ldc + col]) = v;
        }
    }
}

// ---------------------------------------------------------------------------
// Row softmax in place: one block per row of length SEQ=2048, 256 threads,
// 8 elements per thread held in registers (2x float4).
// ---------------------------------------------------------------------------
__global__ __launch_bounds__(256) void softmax_rows_kernel(float* __restrict__ w)
{
    float* p = w + (long)blockIdx.x * SEQ;
    const int tid  = threadIdx.x;
    const int lane = tid & 31;
    const int warp = tid >> 5;

    float4 v0 = *reinterpret_cast<const float4*>(&p[tid * 4]);
    float4 v1 = *reinterpret_cast<const float4*>(&p[tid * 4 + 1024]);

    // --- max reduce
    float m = fmaxf(fmaxf(fmaxf(v0.x, v0.y), fmaxf(v0.z, v0.w)),
                    fmaxf(fmaxf(v1.x, v1.y), fmaxf(v1.z, v1.w)));
    __shared__ float red[8];
#pragma unroll
    for (int o = 16; o; o >>= 1) m = fmaxf(m, __shfl_xor_sync(0xffffffffu, m, o));
    if (lane == 0) red[warp] = m;
    __syncthreads();
    float rmax = red[0];
#pragma unroll
    for (int i = 1; i < 8; i++) rmax = fmaxf(rmax, red[i]);
    __syncthreads();

    // --- exp + sum
    v0.x = __expf(v0.x - rmax); v0.y = __expf(v0.y - rmax);
    v0.z = __expf(v0.z - rmax); v0.w = __expf(v0.w - rmax);
    v1.x = __expf(v1.x - rmax); v1.y = __expf(v1.y - rmax);
    v1.z = __expf(v1.z - rmax); v1.w = __expf(v1.w - rmax);
    float s = v0.x + v0.y + v0.z + v0.w + v1.x + v1.y + v1.z + v1.w;
#pragma unroll
    for (int o = 16; o; o >>= 1) s += __shfl_xor_sync(0xffffffffu, s, o);
    if (lane == 0) red[warp] = s;
    __syncthreads();
    float tot = 0.0f;
#pragma unroll
    for (int i = 0; i < 8; i++) tot += red[i];
    const float inv = 1.0f / tot;

    v0.x *= inv; v0.y *= inv; v0.z *= inv; v0.w *= inv;
    v1.x *= inv; v1.y *= inv; v1.z *= inv; v1.w *= inv;
    *reinterpret_cast<float4*>(&p[tid * 4])        = v0;
    *reinterpret_cast<float4*>(&p[tid * 4 + 1024]) = v1;
}

// ---------------------------------------------------------------------------
extern "C" void kernel_launch(void* const* d_in, const int* in_sizes, int n_in,
                              void* d_out, int out_size)
{
    const float* x  = (const float*)d_in[0];   // [4,2048,1024]
    const float* Wq = (const float*)d_in[1];   // [3072,1024]
    const float* bq = (const float*)d_in[2];   // [3072]

    float* out_attn = (float*)d_out;                       // [4,2048,1024]
    float* out_w    = out_attn + (long)ROWS * DIM;         // [4,2048,2048]

    float* qkv = nullptr;
    cudaGetSymbolAddress((void**)&qkv, g_qkv);

    const float inv_scale = 1.0f / 32.0f;  // 1/sqrt(1024)

    // 1) qkv = x @ W^T + b : M=8192, N=3072, K=1024 (NT, bias)
    {
        dim3 grid(TDIM / BN, ROWS / BM, 1);
        sgemm_kernel<true, true><<<grid, NTHREADS>>>(
            x, Wq, bq, qkv,
            DIM, DIM, DIM, TDIM,
            0, 0, 0, 1.0f);
    }

    // 2) scores = Q @ K^T / 32 per batch : M=N=2048, K=1024 (NT, batched)
    {
        dim3 grid(SEQ / BN, SEQ / BM, BATCH);
        sgemm_kernel<true, false><<<grid, NTHREADS>>>(
            qkv,            /* Q at col 0   */
            qkv + DIM,      /* K at col 1024 */
            nullptr, out_w,
            DIM, TDIM, TDIM, SEQ,
            (long)SEQ * TDIM, (long)SEQ * TDIM, (long)SEQ * SEQ,
            inv_scale);
    }

    // 3) softmax rows in place on w
    softmax_rows_kernel<<<ROWS, 256>>>(out_w);

    // 4) out = w @ V per batch : M=2048, N=1024, K=2048 (NN, batched)
    {
        dim3 grid(DIM / BN, SEQ / BM, BATCH);
        sgemm_kernel<false, false><<<grid, NTHREADS>>>(
            out_w,
            qkv + 2 * DIM,  /* V at col 2048 */
            nullptr, out_attn,
            SEQ, SEQ, TDIM, DIM,
            (long)SEQ * SEQ, (long)SEQ * TDIM, (long)SEQ * DIM,
            1.0f);
    }
}

// round 3
// speedup vs baseline: 2.1892x; 2.1892x over previous
#include <cuda_runtime.h>
#include <cuda_bf16.h>
#include <cstdint>

// ---------------------------------------------------------------------------
// MaskedAttention via mma.sync bf16 hi/lo split (emulated fp32) GEMMs.
// B=4, S=2048, D=1024. Outputs: [out (B*S*D) | w (B*S*S)] fp32.
// All GEMMs are NT: C[m,n] = scale * sum_k A[m,k] * B[n,k] (+ bias[n]).
// ---------------------------------------------------------------------------

#define BATCH 4
#define SEQ   2048
#define DIM   1024
#define ROWS  (BATCH * SEQ)      // 8192

__device__ float g_qk[(long)ROWS * 2 * DIM];          // [8192][2048] Q|K
__device__ float g_vt[(long)BATCH * DIM * SEQ];       // [4][1024][2048] V^T

// ---- smem plan (dynamic, 128 KB) ----
// raw fp32 stage: 2 x 32KB  (A 16KB | B 16KB)
// bf16 tiles:     2 x 32KB  (A hi+lo 16KB | B hi+lo 16KB), SW chunk-xor swizzle
#define STAGE 32768
#define BFOFF 65536
#define SMEM_TOTAL 131072

__device__ __forceinline__ uint32_t smem_u32(const void* p) {
    uint32_t a;
    asm("{ .reg .u64 t; cvta.to.shared.u64 t, %1; cvt.u32.u64 %0, t; }"
        : "=r"(a) : "l"(p));
    return a;
}
__device__ __forceinline__ void cp_async16(uint32_t s, const void* g) {
    asm volatile("cp.async.cg.shared.global [%0], [%1], 16;" :: "r"(s), "l"(g));
}
__device__ __forceinline__ void cp_commit() {
    asm volatile("cp.async.commit_group;" ::: "memory");
}
template <int N>
__device__ __forceinline__ void cp_wait() {
    asm volatile("cp.async.wait_group %0;" :: "n"(N) : "memory");
}
__device__ __forceinline__ void ldsm4(uint32_t* r, uint32_t addr) {
    asm volatile("ldmatrix.sync.aligned.m8n8.x4.shared.b16 {%0,%1,%2,%3}, [%4];"
                 : "=r"(r[0]), "=r"(r[1]), "=r"(r[2]), "=r"(r[3]) : "r"(addr));
}
__device__ __forceinline__ void hmma(float* c, const uint32_t* a, uint32_t b0, uint32_t b1) {
    asm volatile(
        "mma.sync.aligned.m16n8k16.row.col.f32.bf16.bf16.f32 "
        "{%0,%1,%2,%3}, {%4,%5,%6,%7}, {%8,%9}, {%0,%1,%2,%3};"
        : "+f"(c[0]), "+f"(c[1]), "+f"(c[2]), "+f"(c[3])
        : "r"(a[0]), "r"(a[1]), "r"(a[2]), "r"(a[3]), "r"(b0), "r"(b1));
}

// convert one raw fp32 chunk (A|B, 2048 float4) to swizzled bf16 hi/lo tiles
__device__ __forceinline__ void cvt_chunk(const char* raw, char* bf, int tid)
{
#pragma unroll
    for (int t = 0; t < 8; t++) {
        const int i = tid + t * 256;                 // 0..2047
        float4 v = *reinterpret_cast<const float4*>(raw + (long)i * 16);
        const int row  = (i & 1023) >> 3;            // 0..127
        const int sub  = i & 7;                      // which 4-float group in row
        const int chunk = sub >> 1;                  // 16B chunk 0..3 (hi)
        const int off8  = (sub & 1) << 3;            // byte offset inside chunk
        char* base = bf + ((i < 1024) ? 0 : 16384);

        __nv_bfloat16 h0 = __float2bfloat16_rn(v.x);
        __nv_bfloat16 h1 = __float2bfloat16_rn(v.y);
        __nv_bfloat16 h2 = __float2bfloat16_rn(v.z);
        __nv_bfloat16 h3 = __float2bfloat16_rn(v.w);
        __nv_bfloat16 l0 = __float2bfloat16_rn(v.x - __bfloat162float(h0));
        __nv_bfloat16 l1 = __float2bfloat16_rn(v.y - __bfloat162float(h1));
        __nv_bfloat16 l2 = __float2bfloat16_rn(v.z - __bfloat162float(h2));
        __nv_bfloat16 l3 = __float2bfloat16_rn(v.w - __bfloat162float(h3));

        __nv_bfloat162 ph0 = __halves2bfloat162(h0, h1);
        __nv_bfloat162 ph1 = __halves2bfloat162(h2, h3);
        __nv_bfloat162 pl0 = __halves2bfloat162(l0, l1);
        __nv_bfloat162 pl1 = __halves2bfloat162(l2, l3);
        uint2 uh = make_uint2(*reinterpret_cast<uint32_t*>(&ph0),
                              *reinterpret_cast<uint32_t*>(&ph1));
        uint2 ul = make_uint2(*reinterpret_cast<uint32_t*>(&pl0),
                              *reinterpret_cast<uint32_t*>(&pl1));

        const int r7 = row & 7;
        *reinterpret_cast<uint2*>(base + row * 128 + ((chunk ^ r7) << 4) + off8) = uh;
        *reinterpret_cast<uint2*>(base + row * 128 + (((chunk + 4) ^ r7) << 4) + off8) = ul;
    }
}

// ---------------------------------------------------------------------------
template <bool BIAS, bool VSPLIT>
__global__ __launch_bounds__(256) void mma_gemm(
    const float* __restrict__ Ab, const float* __restrict__ Bb,
    const float* __restrict__ bias,
    float* __restrict__ Cb, float* __restrict__ Cv,
    int K, int lda, int ldb, int ldc,
    long sA, long sB, long sC, float scale)
{
    extern __shared__ char ds[];
    const int tid  = threadIdx.x;
    const int wid  = tid >> 5;
    const int lane = tid & 31;
    const int bm   = blockIdx.y * 128;
    const int bn   = blockIdx.x * 128;
    const int z    = blockIdx.z;

    const float* A = Ab + (long)z * sA + (long)bm * lda;
    const float* B = Bb + (long)z * sB + (long)bn * ldb;

    const int wm = (wid >> 2) << 6;     // 0 or 64
    const int wn = (wid & 3) << 5;      // 0,32,64,96

    float acc[4][4][4];
#pragma unroll
    for (int a = 0; a < 4; a++)
#pragma unroll
        for (int b = 0; b < 4; b++)
#pragma unroll
            for (int c = 0; c < 4; c++) acc[a][b][c] = 0.0f;

    const int nck = K >> 5;   // 32-float K chunks

    // issue cp.async for a chunk ck into raw stage st
    auto issue = [&](int ck, int st) {
        const int k0 = ck << 5;
        uint32_t s = smem_u32(ds) + st * STAGE;
#pragma unroll
        for (int t = 0; t < 8; t++) {
            const int i = tid + t * 256;
            const int i2 = i & 1023;
            const int row = i2 >> 3, col = (i2 & 7) << 2;
            const float* g = (i < 1024) ? (A + (long)row * lda + k0 + col)
                                        : (B + (long)row * ldb + k0 + col);
            cp_async16(s + i * 16, g);
        }
        cp_commit();
    };

    issue(0, 0);
    if (nck > 1) issue(1, 1);
    cp_wait<1>();
    __syncthreads();
    cvt_chunk(ds, ds + BFOFF, tid);
    __syncthreads();

    const uint32_t bfbase = smem_u32(ds) + BFOFF;
    // per-lane ldmatrix address components
    const int j = lane >> 3;
    const int arow = ((j & 1) << 3) | (lane & 7);    // A: row offset in m16 tile
    const int acnk = j >> 1;                         // A: chunk offset (0/1)
    const int brow = ((j >> 1) << 3) | (lane & 7);   // B: row offset in n16 group
    const int bcnk = j & 1;                          // B: chunk offset (0/1)
    const int r7a = arow & 7;
    const int r7b = brow & 7;

    for (int ck = 0; ck < nck; ck++) {
        const uint32_t bfA = bfbase + (ck & 1) * STAGE;
        const uint32_t bfB = bfA + 16384;

        // ---- compute chunk ck: 2 k16 steps
#pragma unroll
        for (int s = 0; s < 2; s++) {
            const int c0 = s * 2;
            uint32_t ah[4][4], al[4][4], bh[2][4], bl[2][4];
#pragma unroll
            for (int mt = 0; mt < 4; mt++) {
                const int r = wm + (mt << 4) + arow;
                const uint32_t rb = bfA + r * 128;
                ldsm4(ah[mt], rb + (((c0 + acnk) ^ r7a) << 4));
                ldsm4(al[mt], rb + (((c0 + acnk + 4) ^ r7a) << 4));
            }
#pragma unroll
            for (int nt2 = 0; nt2 < 2; nt2++) {
                const int r = wn + (nt2 << 4) + brow;
                const uint32_t rb = bfB + r * 128;
                ldsm4(bh[nt2], rb + (((c0 + bcnk) ^ r7b) << 4));
                ldsm4(bl[nt2], rb + (((c0 + bcnk + 4) ^ r7b) << 4));
            }
#pragma unroll
            for (int mt = 0; mt < 4; mt++)
#pragma unroll
                for (int nt = 0; nt < 4; nt++) {
                    const int g = nt >> 1, p = (nt & 1) << 1;
                    hmma(acc[mt][nt], ah[mt], bh[g][p], bh[g][p + 1]);
                    hmma(acc[mt][nt], ah[mt], bl[g][p], bl[g][p + 1]);
                    hmma(acc[mt][nt], al[mt], bh[g][p], bh[g][p + 1]);
                }
        }

        // ---- overlap: convert chunk ck+1 while other warps still compute
        if (ck + 1 < nck) {
            cp_wait<0>();
            cvt_chunk(ds + ((ck + 1) & 1) * STAGE, (char*)(ds + BFOFF) + ((ck + 1) & 1) * STAGE, tid);
        }
        __syncthreads();
        if (ck + 2 < nck) issue(ck + 2, ck & 1);
    }

    // ---- epilogue
    const int mrow = lane >> 2;
    const int ncol = (lane & 3) << 1;
    if (!VSPLIT || bn < 2048) {
        float* C = Cb + (long)z * sC;
#pragma unroll
        for (int mt = 0; mt < 4; mt++) {
            const int m = bm + wm + (mt << 4) + mrow;
#pragma unroll
            for (int nt = 0; nt < 4; nt++) {
                const int n = bn + wn + (nt << 3) + ncol;
                float b0 = 0.f, b1 = 0.f;
                if (BIAS) { b0 = bias[n]; b1 = bias[n + 1]; }
                float2 v0 = make_float2(acc[mt][nt][0] * scale + b0,
                                        acc[mt][nt][1] * scale + b1);
                float2 v1 = make_float2(acc[mt][nt][2] * scale + b0,
                                        acc[mt][nt][3] * scale + b1);
                *reinterpret_cast<float2*>(C + (long)m * ldc + n) = v0;
                *reinterpret_cast<float2*>(C + (long)(m + 8) * ldc + n) = v1;
            }
        }
    } else {
        // V part: write transposed into Cv as V^T[b][d][s]
#pragma unroll
        for (int mt = 0; mt < 4; mt++) {
            const int m = bm + wm + (mt << 4) + mrow;
            const int b0i = m >> 11, s0 = m & 2047;
            const int b1i = (m + 8) >> 11, s1 = (m + 8) & 2047;
#pragma unroll
            for (int nt = 0; nt < 4; nt++) {
                const int n = bn + wn + (nt << 3) + ncol;
                const int d = n - 2048;
                float bb0 = 0.f, bb1 = 0.f;
                if (BIAS) { bb0 = bias[n]; bb1 = bias[n + 1]; }
                Cv[(long)b0i * DIM * SEQ + (long)d * SEQ + s0]       = acc[mt][nt][0] + bb0;
                Cv[(long)b0i * DIM * SEQ + (long)(d + 1) * SEQ + s0] = acc[mt][nt][1] + bb1;
                Cv[(long)b1i * DIM * SEQ + (long)d * SEQ + s1]       = acc[mt][nt][2] + bb0;
                Cv[(long)b1i * DIM * SEQ + (long)(d + 1) * SEQ + s1] = acc[mt][nt][3] + bb1;
            }
        }
    }
}

// ---------------------------------------------------------------------------
__global__ __launch_bounds__(256) void softmax_rows_kernel(float* __restrict__ w)
{
    float* p = w + (long)blockIdx.x * SEQ;
    const int tid  = threadIdx.x;
    const int lane = tid & 31;
    const int warp = tid >> 5;

    float4 v0 = *reinterpret_cast<const float4*>(&p[tid * 4]);
    float4 v1 = *reinterpret_cast<const float4*>(&p[tid * 4 + 1024]);

    float m = fmaxf(fmaxf(fmaxf(v0.x, v0.y), fmaxf(v0.z, v0.w)),
                    fmaxf(fmaxf(v1.x, v1.y), fmaxf(v1.z, v1.w)));
    __shared__ float red[8];
#pragma unroll
    for (int o = 16; o; o >>= 1) m = fmaxf(m, __shfl_xor_sync(0xffffffffu, m, o));
    if (lane == 0) red[warp] = m;
    __syncthreads();
    float rmax = red[0];
#pragma unroll
    for (int i = 1; i < 8; i++) rmax = fmaxf(rmax, red[i]);
    __syncthreads();

    v0.x = __expf(v0.x - rmax); v0.y = __expf(v0.y - rmax);
    v0.z = __expf(v0.z - rmax); v0.w = __expf(v0.w - rmax);
    v1.x = __expf(v1.x - rmax); v1.y = __expf(v1.y - rmax);
    v1.z = __expf(v1.z - rmax); v1.w = __expf(v1.w - rmax);
    float s = v0.x + v0.y + v0.z + v0.w + v1.x + v1.y + v1.z + v1.w;
#pragma unroll
    for (int o = 16; o; o >>= 1) s += __shfl_xor_sync(0xffffffffu, s, o);
    if (lane == 0) red[warp] = s;
    __syncthreads();
    float tot = 0.0f;
#pragma unroll
    for (int i = 0; i < 8; i++) tot += red[i];
    const float inv = 1.0f / tot;

    v0.x *= inv; v0.y *= inv; v0.z *= inv; v0.w *= inv;
    v1.x *= inv; v1.y *= inv; v1.z *= inv; v1.w *= inv;
    *reinterpret_cast<float4*>(&p[tid * 4])        = v0;
    *reinterpret_cast<float4*>(&p[tid * 4 + 1024]) = v1;
}

// ---------------------------------------------------------------------------
extern "C" void kernel_launch(void* const* d_in, const int* in_sizes, int n_in,
                              void* d_out, int out_size)
{
    const float* x  = (const float*)d_in[0];   // [4,2048,1024]
    const float* Wq = (const float*)d_in[1];   // [3072,1024]
    const float* bq = (const float*)d_in[2];   // [3072]

    float* out_attn = (float*)d_out;                   // [4,2048,1024]
    float* out_w    = out_attn + (long)ROWS * DIM;     // [4,2048,2048]

    float *qk = nullptr, *vt = nullptr;
    cudaGetSymbolAddress((void**)&qk, g_qk);
    cudaGetSymbolAddress((void**)&vt, g_vt);

    cudaFuncSetAttribute(mma_gemm<true, true>,
                         cudaFuncAttributeMaxDynamicSharedMemorySize, SMEM_TOTAL);
    cudaFuncSetAttribute(mma_gemm<false, false>,
                         cudaFuncAttributeMaxDynamicSharedMemorySize, SMEM_TOTAL);

    // 1) qkv = x @ W^T + b : M=8192, N=3072, K=1024
    //    cols <2048 -> g_qk (Q|K row-major); cols >=2048 -> g_vt transposed
    mma_gemm<true, true><<<dim3(24, 64, 1), 256, SMEM_TOTAL>>>(
        x, Wq, bq, qk, vt,
        1024, 1024, 1024, 2048, 0, 0, 0, 1.0f);

    // 2) scores = Q @ K^T / 32 : M=N=2048, K=1024, batched
    mma_gemm<false, false><<<dim3(16, 16, BATCH), 256, SMEM_TOTAL>>>(
        qk, qk + 1024, nullptr, out_w, nullptr,
        1024, 2048, 2048, 2048,
        (long)SEQ * 2048, (long)SEQ * 2048, (long)SEQ * SEQ, 1.0f / 32.0f);

    // 3) softmax rows in place
    softmax_rows_kernel<<<ROWS, 256>>>(out_w);

    // 4) out = w @ V : M=2048, N=1024, K=2048 (B = V^T, K-major), batched
    mma_gemm<false, false><<<dim3(8, 16, BATCH), 256, SMEM_TOTAL>>>(
        out_w, vt, nullptr, out_attn, nullptr,
        2048, 2048, 2048, 1024,
        (long)SEQ * SEQ, (long)DIM * SEQ, (long)SEQ * DIM, 1.0f);
}

// round 4
// speedup vs baseline: 2.8502x; 1.3020x over previous
#include <cuda_runtime.h>
#include <cuda_bf16.h>
#include <cstdint>

// ---------------------------------------------------------------------------
// MaskedAttention via mma.sync bf16 hi/lo split (emulated fp32) GEMMs.
// GEMM1 writes Q/K/V^T directly as bf16 hi/lo planes so downstream GEMMs
// skip conversion (GEMM2 entirely; GEMM4 converts only A=w).
// All GEMMs NT: C[m,n] = scale * sum_k A[m,k]*B[n,k] (+ bias[n]).
// ---------------------------------------------------------------------------

#define BATCH 4
#define SEQ   2048
#define DIM   1024
#define ROWS  (BATCH * SEQ)      // 8192

__device__ __nv_bfloat16 g_qkh[(long)ROWS * 2048];        // Q|K hi plane
__device__ __nv_bfloat16 g_qkl[(long)ROWS * 2048];        // Q|K lo plane
__device__ __nv_bfloat16 g_vth[(long)BATCH * DIM * SEQ];  // V^T hi
__device__ __nv_bfloat16 g_vtl[(long)BATCH * DIM * SEQ];  // V^T lo

// smem: 2 buffers x 32KB; per buffer A tile 16KB (row*128: hi chunks0-3|lo 4-7,
// chunk xor row&7 swizzle) + B tile 16KB at +16384.
#define BUF 32768
#define SMEM_TOTAL 65536

__device__ __forceinline__ uint32_t smem_u32(const void* p) {
    uint32_t a;
    asm("{ .reg .u64 t; cvta.to.shared.u64 t, %1; cvt.u32.u64 %0, t; }"
        : "=r"(a) : "l"(p));
    return a;
}
__device__ __forceinline__ void cp_async16(uint32_t s, const void* g) {
    asm volatile("cp.async.cg.shared.global [%0], [%1], 16;" :: "r"(s), "l"(g));
}
__device__ __forceinline__ void cp_commit() {
    asm volatile("cp.async.commit_group;" ::: "memory");
}
template <int N>
__device__ __forceinline__ void cp_wait() {
    asm volatile("cp.async.wait_group %0;" :: "n"(N) : "memory");
}
__device__ __forceinline__ void ldsm4(uint32_t* r, uint32_t addr) {
    asm volatile("ldmatrix.sync.aligned.m8n8.x4.shared.b16 {%0,%1,%2,%3}, [%4];"
                 : "=r"(r[0]), "=r"(r[1]), "=r"(r[2]), "=r"(r[3]) : "r"(addr));
}
__device__ __forceinline__ void hmma(float* c, const uint32_t* a, uint32_t b0, uint32_t b1) {
    asm volatile(
        "mma.sync.aligned.m16n8k16.row.col.f32.bf16.bf16.f32 "
        "{%0,%1,%2,%3}, {%4,%5,%6,%7}, {%8,%9}, {%0,%1,%2,%3};"
        : "+f"(c[0]), "+f"(c[1]), "+f"(c[2]), "+f"(c[3])
        : "r"(a[0]), "r"(a[1]), "r"(a[2]), "r"(a[3]), "r"(b0), "r"(b1));
}

// split fp32 float4 -> swizzled hi/lo bf16 in smem region (i in [0,1024))
__device__ __forceinline__ void cvt_store4(char* region, int i, float4 v)
{
    const int row  = i >> 3;
    const int sub  = i & 7;
    const int chunk = sub >> 1;
    const int off8  = (sub & 1) << 3;
    const int r7 = row & 7;

    __nv_bfloat16 h0 = __float2bfloat16_rn(v.x);
    __nv_bfloat16 h1 = __float2bfloat16_rn(v.y);
    __nv_bfloat16 h2 = __float2bfloat16_rn(v.z);
    __nv_bfloat16 h3 = __float2bfloat16_rn(v.w);
    __nv_bfloat16 l0 = __float2bfloat16_rn(v.x - __bfloat162float(h0));
    __nv_bfloat16 l1 = __float2bfloat16_rn(v.y - __bfloat162float(h1));
    __nv_bfloat16 l2 = __float2bfloat16_rn(v.z - __bfloat162float(h2));
    __nv_bfloat16 l3 = __float2bfloat16_rn(v.w - __bfloat162float(h3));

    __nv_bfloat162 ph0 = __halves2bfloat162(h0, h1);
    __nv_bfloat162 ph1 = __halves2bfloat162(h2, h3);
    __nv_bfloat162 pl0 = __halves2bfloat162(l0, l1);
    __nv_bfloat162 pl1 = __halves2bfloat162(l2, l3);
    uint2 uh = make_uint2(*reinterpret_cast<uint32_t*>(&ph0),
                          *reinterpret_cast<uint32_t*>(&ph1));
    uint2 ul = make_uint2(*reinterpret_cast<uint32_t*>(&pl0),
                          *reinterpret_cast<uint32_t*>(&pl1));
    *reinterpret_cast<uint2*>(region + row * 128 + ((chunk ^ r7) << 4) + off8) = uh;
    *reinterpret_cast<uint2*>(region + row * 128 + (((chunk + 4) ^ r7) << 4) + off8) = ul;
}

// ---------------------------------------------------------------------------
// AM/BM: 0 = fp32 source (LDG + convert), 1 = bf16 hi/lo planes (cp.async).
// EPI:   0 = fp32 C (scale), 1 = GEMM1 split epilogue (+bias, write planes).
// ---------------------------------------------------------------------------
template <int AM, int BM, int EPI>
__global__ __launch_bounds__(256, 2) void mma_gemm(
    const float* __restrict__ Af,
    const __nv_bfloat16* __restrict__ Ahp, const __nv_bfloat16* __restrict__ Alp,
    const float* __restrict__ Bf,
    const __nv_bfloat16* __restrict__ Bhp, const __nv_bfloat16* __restrict__ Blp,
    const float* __restrict__ bias, float* __restrict__ C,
    __nv_bfloat16* __restrict__ qkh, __nv_bfloat16* __restrict__ qkl,
    __nv_bfloat16* __restrict__ vth, __nv_bfloat16* __restrict__ vtl,
    int K, int lda, int ldb, int ldc,
    long sA, long sB, long sC, float scale)
{
    extern __shared__ char ds[];
    const int tid  = threadIdx.x;
    const int wid  = tid >> 5;
    const int lane = tid & 31;
    const int bm   = blockIdx.y * 128;
    const int bn   = blockIdx.x * 128;
    const int z    = blockIdx.z;

    if (AM == 0) Af  += z * sA + (long)bm * lda;
    else        { Ahp += z * sA + (long)bm * lda; Alp += z * sA + (long)bm * lda; }
    if (BM == 0) Bf  += z * sB + (long)bn * ldb;
    else        { Bhp += z * sB + (long)bn * ldb; Blp += z * sB + (long)bn * ldb; }

    const int wm = (wid >> 2) << 6;     // 0 or 64
    const int wn = (wid & 3) << 5;      // 0,32,64,96

    float acc[4][4][4];
#pragma unroll
    for (int a = 0; a < 4; a++)
#pragma unroll
        for (int b = 0; b < 4; b++)
#pragma unroll
            for (int c = 0; c < 4; c++) acc[a][b][c] = 0.0f;

    const int nck = K >> 5;
    constexpr bool ANYD = (AM == 1) || (BM == 1);

    const uint32_t sb0 = smem_u32(ds);

    // ---- direct (bf16 plane) cp.async for chunk ck into buffer p
    auto issue_direct = [&](int ck, int p) {
        const int k0 = ck << 5;
        const uint32_t sbase = sb0 + p * BUF;
        if (AM == 1) {
#pragma unroll
            for (int t = 0; t < 4; t++) {
                const int i = tid + t * 256;
                const int pl = i >> 9, j = i & 511, r = j >> 2, cc = j & 3;
                const __nv_bfloat16* src =
                    (pl ? Alp : Ahp) + (long)r * lda + k0 + cc * 8;
                const uint32_t dst = sbase + r * 128 +
                    (((cc + (pl ? 4 : 0)) ^ (r & 7)) << 4);
                cp_async16(dst, src);
            }
        }
        if (BM == 1) {
#pragma unroll
            for (int t = 0; t < 4; t++) {
                const int i = tid + t * 256;
                const int pl = i >> 9, j = i & 511, r = j >> 2, cc = j & 3;
                const __nv_bfloat16* src =
                    (pl ? Blp : Bhp) + (long)r * ldb + k0 + cc * 8;
                const uint32_t dst = sbase + 16384 + r * 128 +
                    (((cc + (pl ? 4 : 0)) ^ (r & 7)) << 4);
                cp_async16(dst, src);
            }
        }
        if (ANYD) cp_commit();
    };

    float4 avA[4], avB[4];
    auto ldg_cvt = [&](int ck) {
        const int k0 = ck << 5;
        if (AM == 0) {
#pragma unroll
            for (int t = 0; t < 4; t++) {
                const int i = tid + t * 256;
                avA[t] = *reinterpret_cast<const float4*>(
                    Af + (long)(i >> 3) * lda + k0 + ((i & 7) << 2));
            }
        }
        if (BM == 0) {
#pragma unroll
            for (int t = 0; t < 4; t++) {
                const int i = tid + t * 256;
                avB[t] = *reinterpret_cast<const float4*>(
                    Bf + (long)(i >> 3) * ldb + k0 + ((i & 7) << 2));
            }
        }
    };
    auto cvt_store = [&](int p) {
        char* base = ds + p * BUF;
        if (AM == 0) {
#pragma unroll
            for (int t = 0; t < 4; t++) cvt_store4(base, tid + t * 256, avA[t]);
        }
        if (BM == 0) {
#pragma unroll
            for (int t = 0; t < 4; t++) cvt_store4(base + 16384, tid + t * 256, avB[t]);
        }
    };

    // ---- prologue: fill buffer 0
    issue_direct(0, 0);
    ldg_cvt(0);
    cvt_store(0);
    if (ANYD) cp_wait<0>();
    __syncthreads();

    // per-lane ldmatrix address components
    const int j = lane >> 3;
    const int arow = ((j & 1) << 3) | (lane & 7);
    const int acnk = j >> 1;
    const int brow = ((j >> 1) << 3) | (lane & 7);
    const int bcnk = j & 1;
    const int r7a = arow & 7;
    const int r7b = brow & 7;

    for (int ck = 0; ck < nck; ck++) {
        const int p = ck & 1;
        if (ck + 1 < nck) {
            issue_direct(ck + 1, p ^ 1);
            ldg_cvt(ck + 1);
        }

        const uint32_t bfA = sb0 + p * BUF;
        const uint32_t bfB = bfA + 16384;
#pragma unroll
        for (int s = 0; s < 2; s++) {
            const int c0 = s * 2;
            uint32_t ah[4][4], al[4][4], bh[2][4], bl[2][4];
#pragma unroll
            for (int mt = 0; mt < 4; mt++) {
                const int r = wm + (mt << 4) + arow;
                const uint32_t rb = bfA + r * 128;
                ldsm4(ah[mt], rb + (((c0 + acnk) ^ r7a) << 4));
                ldsm4(al[mt], rb + (((c0 + acnk + 4) ^ r7a) << 4));
            }
#pragma unroll
            for (int nt2 = 0; nt2 < 2; nt2++) {
                const int r = wn + (nt2 << 4) + brow;
                const uint32_t rb = bfB + r * 128;
                ldsm4(bh[nt2], rb + (((c0 + bcnk) ^ r7b) << 4));
                ldsm4(bl[nt2], rb + (((c0 + bcnk + 4) ^ r7b) << 4));
            }
#pragma unroll
            for (int mt = 0; mt < 4; mt++)
#pragma unroll
                for (int nt = 0; nt < 4; nt++) {
                    const int g = nt >> 1, q = (nt & 1) << 1;
                    hmma(acc[mt][nt], ah[mt], bh[g][q], bh[g][q + 1]);
                    hmma(acc[mt][nt], ah[mt], bl[g][q], bl[g][q + 1]);
                    hmma(acc[mt][nt], al[mt], bh[g][q], bh[g][q + 1]);
                }
        }

        if (ck + 1 < nck) {
            cvt_store(p ^ 1);
            if (ANYD) cp_wait<0>();
        }
        __syncthreads();
    }

    // ---- epilogue
    const int mrow = lane >> 2;
    const int ncol = (lane & 3) << 1;
    if (EPI == 0) {
        float* Cz = C + (long)z * sC;
#pragma unroll
        for (int mt = 0; mt < 4; mt++) {
            const int m = bm + wm + (mt << 4) + mrow;
#pragma unroll
            for (int nt = 0; nt < 4; nt++) {
                const int n = bn + wn + (nt << 3) + ncol;
                float2 v0 = make_float2(acc[mt][nt][0] * scale, acc[mt][nt][1] * scale);
                float2 v1 = make_float2(acc[mt][nt][2] * scale, acc[mt][nt][3] * scale);
                *reinterpret_cast<float2*>(Cz + (long)m * ldc + n) = v0;
                *reinterpret_cast<float2*>(Cz + (long)(m + 8) * ldc + n) = v1;
            }
        }
    } else {
#pragma unroll
        for (int mt = 0; mt < 4; mt++) {
            const int m0 = bm + wm + (mt << 4) + mrow;
            const int m1 = m0 + 8;
#pragma unroll
            for (int nt = 0; nt < 4; nt++) {
                const int n = bn + wn + (nt << 3) + ncol;
                const float b0 = bias[n], b1 = bias[n + 1];
                float v00 = acc[mt][nt][0] + b0, v01 = acc[mt][nt][1] + b1;
                float v10 = acc[mt][nt][2] + b0, v11 = acc[mt][nt][3] + b1;
                __nv_bfloat16 h00 = __float2bfloat16_rn(v00);
                __nv_bfloat16 h01 = __float2bfloat16_rn(v01);
                __nv_bfloat16 h10 = __float2bfloat16_rn(v10);
                __nv_bfloat16 h11 = __float2bfloat16_rn(v11);
                __nv_bfloat16 l00 = __float2bfloat16_rn(v00 - __bfloat162float(h00));
                __nv_bfloat16 l01 = __float2bfloat16_rn(v01 - __bfloat162float(h01));
                __nv_bfloat16 l10 = __float2bfloat16_rn(v10 - __bfloat162float(h10));
                __nv_bfloat16 l11 = __float2bfloat16_rn(v11 - __bfloat162float(h11));
                if (n < 2048) {
                    __nv_bfloat162 ph0 = __halves2bfloat162(h00, h01);
                    __nv_bfloat162 pl0 = __halves2bfloat162(l00, l01);
                    __nv_bfloat162 ph1 = __halves2bfloat162(h10, h11);
                    __nv_bfloat162 pl1 = __halves2bfloat162(l10, l11);
                    *reinterpret_cast<__nv_bfloat162*>(&qkh[(long)m0 * 2048 + n]) = ph0;
                    *reinterpret_cast<__nv_bfloat162*>(&qkl[(long)m0 * 2048 + n]) = pl0;
                    *reinterpret_cast<__nv_bfloat162*>(&qkh[(long)m1 * 2048 + n]) = ph1;
                    *reinterpret_cast<__nv_bfloat162*>(&qkl[(long)m1 * 2048 + n]) = pl1;
                } else {
                    const int d = n - 2048;
                    const int bi0 = m0 >> 11, s0 = m0 & 2047;
                    const int bi1 = m1 >> 11, s1 = m1 & 2047;
                    __nv_bfloat16* th0 = vth + (long)bi0 * DIM * SEQ + (long)d * SEQ + s0;
                    __nv_bfloat16* tl0 = vtl + (long)bi0 * DIM * SEQ + (long)d * SEQ + s0;
                    __nv_bfloat16* th1 = vth + (long)bi1 * DIM * SEQ + (long)d * SEQ + s1;
                    __nv_bfloat16* tl1 = vtl + (long)bi1 * DIM * SEQ + (long)d * SEQ + s1;
                    th0[0] = h00; th0[SEQ] = h01; tl0[0] = l00; tl0[SEQ] = l01;
                    th1[0] = h10; th1[SEQ] = h11; tl1[0] = l10; tl1[SEQ] = l11;
                }
            }
        }
    }
}

// ---------------------------------------------------------------------------
__global__ __launch_bounds__(256) void softmax_rows_kernel(float* __restrict__ w)
{
    float* p = w + (long)blockIdx.x * SEQ;
    const int tid  = threadIdx.x;
    const int lane = tid & 31;
    const int warp = tid >> 5;

    float4 v0 = *reinterpret_cast<const float4*>(&p[tid * 4]);
    float4 v1 = *reinterpret_cast<const float4*>(&p[tid * 4 + 1024]);

    float m = fmaxf(fmaxf(fmaxf(v0.x, v0.y), fmaxf(v0.z, v0.w)),
                    fmaxf(fmaxf(v1.x, v1.y), fmaxf(v1.z, v1.w)));
    __shared__ float red[8];
#pragma unroll
    for (int o = 16; o; o >>= 1) m = fmaxf(m, __shfl_xor_sync(0xffffffffu, m, o));
    if (lane == 0) red[warp] = m;
    __syncthreads();
    float rmax = red[0];
#pragma unroll
    for (int i = 1; i < 8; i++) rmax = fmaxf(rmax, red[i]);
    __syncthreads();

    v0.x = __expf(v0.x - rmax); v0.y = __expf(v0.y - rmax);
    v0.z = __expf(v0.z - rmax); v0.w = __expf(v0.w - rmax);
    v1.x = __expf(v1.x - rmax); v1.y = __expf(v1.y - rmax);
    v1.z = __expf(v1.z - rmax); v1.w = __expf(v1.w - rmax);
    float s = v0.x + v0.y + v0.z + v0.w + v1.x + v1.y + v1.z + v1.w;
#pragma unroll
    for (int o = 16; o; o >>= 1) s += __shfl_xor_sync(0xffffffffu, s, o);
    if (lane == 0) red[warp] = s;
    __syncthreads();
    float tot = 0.0f;
#pragma unroll
    for (int i = 0; i < 8; i++) tot += red[i];
    const float inv = 1.0f / tot;

    v0.x *= inv; v0.y *= inv; v0.z *= inv; v0.w *= inv;
    v1.x *= inv; v1.y *= inv; v1.z *= inv; v1.w *= inv;
    *reinterpret_cast<float4*>(&p[tid * 4])        = v0;
    *reinterpret_cast<float4*>(&p[tid * 4 + 1024]) = v1;
}

// ---------------------------------------------------------------------------
extern "C" void kernel_launch(void* const* d_in, const int* in_sizes, int n_in,
                              void* d_out, int out_size)
{
    const float* x  = (const float*)d_in[0];   // [4,2048,1024]
    const float* Wq = (const float*)d_in[1];   // [3072,1024]
    const float* bq = (const float*)d_in[2];   // [3072]

    float* out_attn = (float*)d_out;                   // [4,2048,1024]
    float* out_w    = out_attn + (long)ROWS * DIM;     // [4,2048,2048]

    __nv_bfloat16 *qkh, *qkl, *vth, *vtl;
    cudaGetSymbolAddress((void**)&qkh, g_qkh);
    cudaGetSymbolAddress((void**)&qkl, g_qkl);
    cudaGetSymbolAddress((void**)&vth, g_vth);
    cudaGetSymbolAddress((void**)&vtl, g_vtl);

    cudaFuncSetAttribute(mma_gemm<0, 0, 1>,
                         cudaFuncAttributeMaxDynamicSharedMemorySize, SMEM_TOTAL);
    cudaFuncSetAttribute(mma_gemm<1, 1, 0>,
                         cudaFuncAttributeMaxDynamicSharedMemorySize, SMEM_TOTAL);
    cudaFuncSetAttribute(mma_gemm<0, 1, 0>,
                         cudaFuncAttributeMaxDynamicSharedMemorySize, SMEM_TOTAL);

    // 1) qkv = x @ W^T + b : M=8192, N=3072, K=1024  (fp32 in, planes out)
    mma_gemm<0, 0, 1><<<dim3(24, 64, 1), 256, SMEM_TOTAL>>>(
        x, nullptr, nullptr, Wq, nullptr, nullptr,
        bq, nullptr, qkh, qkl, vth, vtl,
        1024, 1024, 1024, 0, 0, 0, 0, 1.0f);

    // 2) scores = Q @ K^T / 32 : M=N=2048, K=1024, batched (planes in, fp32 out)
    mma_gemm<1, 1, 0><<<dim3(16, 16, BATCH), 256, SMEM_TOTAL>>>(
        nullptr, qkh, qkl, nullptr, qkh + 1024, qkl + 1024,
        nullptr, out_w, nullptr, nullptr, nullptr, nullptr,
        1024, 2048, 2048, 2048,
        (long)SEQ * 2048, (long)SEQ * 2048, (long)SEQ * SEQ, 1.0f / 32.0f);

    // 3) softmax rows in place
    softmax_rows_kernel<<<ROWS, 256>>>(out_w);

    // 4) out = w @ V : M=2048, N=1024, K=2048 (A=w fp32, B=V^T planes)
    mma_gemm<0, 1, 0><<<dim3(8, 16, BATCH), 256, SMEM_TOTAL>>>(
        out_w, nullptr, nullptr, nullptr, vth, vtl,
        nullptr, out_attn, nullptr, nullptr, nullptr, nullptr,
        2048, 2048, 2048, 1024,
        (long)SEQ * SEQ, (long)DIM * SEQ, (long)SEQ * DIM, 1.0f);
}

// round 5
// speedup vs baseline: 3.1190x; 1.0943x over previous
#include <cuda_runtime.h>
#include <cuda_bf16.h>
#include <cstdint>

// ---------------------------------------------------------------------------
// MaskedAttention, all GEMMs as pure bf16 hi/lo plane mma.sync kernels.
// prepass: x,W -> planes. GEMM1 -> qk planes + v^T planes (bias fused).
// GEMM2 -> fp32 scores. softmax -> fp32 w (output) + w planes.
// GEMM4 -> fp32 out. C[m,n] = scale * sum_k A[m,k]*B[n,k].
// ---------------------------------------------------------------------------

#define BATCH 4
#define SEQ   2048
#define DIM   1024
#define ROWS  (BATCH * SEQ)      // 8192

__device__ __nv_bfloat16 g_xh[(long)ROWS * DIM];
__device__ __nv_bfloat16 g_xl[(long)ROWS * DIM];
__device__ __nv_bfloat16 g_wh[(long)3 * DIM * DIM];
__device__ __nv_bfloat16 g_wl[(long)3 * DIM * DIM];
__device__ __nv_bfloat16 g_qkh[(long)ROWS * 2048];
__device__ __nv_bfloat16 g_qkl[(long)ROWS * 2048];
__device__ __nv_bfloat16 g_vth[(long)BATCH * DIM * SEQ];
__device__ __nv_bfloat16 g_vtl[(long)BATCH * DIM * SEQ];
__device__ __nv_bfloat16 g_wph[(long)ROWS * SEQ];
__device__ __nv_bfloat16 g_wpl[(long)ROWS * SEQ];

// smem: 3 stages x 32KB (A 16KB | B 16KB), chunk-xor swizzled bf16 hi/lo
#define STAGES 3
#define BUF 32768
#define SMEM_TOTAL (STAGES * BUF)

__device__ __forceinline__ uint32_t smem_u32(const void* p) {
    uint32_t a;
    asm("{ .reg .u64 t; cvta.to.shared.u64 t, %1; cvt.u32.u64 %0, t; }"
        : "=r"(a) : "l"(p));
    return a;
}
__device__ __forceinline__ void cp_async16(uint32_t s, const void* g) {
    asm volatile("cp.async.cg.shared.global [%0], [%1], 16;" :: "r"(s), "l"(g));
}
__device__ __forceinline__ void cp_commit() {
    asm volatile("cp.async.commit_group;" ::: "memory");
}
template <int N>
__device__ __forceinline__ void cp_wait() {
    asm volatile("cp.async.wait_group %0;" :: "n"(N) : "memory");
}
__device__ __forceinline__ void ldsm4(uint32_t* r, uint32_t addr) {
    asm volatile("ldmatrix.sync.aligned.m8n8.x4.shared.b16 {%0,%1,%2,%3}, [%4];"
                 : "=r"(r[0]), "=r"(r[1]), "=r"(r[2]), "=r"(r[3]) : "r"(addr));
}
__device__ __forceinline__ void hmma(float* c, const uint32_t* a, uint32_t b0, uint32_t b1) {
    asm volatile(
        "mma.sync.aligned.m16n8k16.row.col.f32.bf16.bf16.f32 "
        "{%0,%1,%2,%3}, {%4,%5,%6,%7}, {%8,%9}, {%0,%1,%2,%3};"
        : "+f"(c[0]), "+f"(c[1]), "+f"(c[2]), "+f"(c[3])
        : "r"(a[0]), "r"(a[1]), "r"(a[2]), "r"(a[3]), "r"(b0), "r"(b1));
}

// ---------------------------------------------------------------------------
// prepass: split fp32 -> bf16 hi/lo planes (grid-stride over float4)
// ---------------------------------------------------------------------------
__global__ __launch_bounds__(256) void split_planes(
    const float* __restrict__ src,
    __nv_bfloat16* __restrict__ hi, __nv_bfloat16* __restrict__ lo, long n4)
{
    for (long i = blockIdx.x * 256 + threadIdx.x; i < n4; i += (long)gridDim.x * 256) {
        float4 v = *reinterpret_cast<const float4*>(src + i * 4);
        __nv_bfloat16 h0 = __float2bfloat16_rn(v.x);
        __nv_bfloat16 h1 = __float2bfloat16_rn(v.y);
        __nv_bfloat16 h2 = __float2bfloat16_rn(v.z);
        __nv_bfloat16 h3 = __float2bfloat16_rn(v.w);
        __nv_bfloat16 l0 = __float2bfloat16_rn(v.x - __bfloat162float(h0));
        __nv_bfloat16 l1 = __float2bfloat16_rn(v.y - __bfloat162float(h1));
        __nv_bfloat16 l2 = __float2bfloat16_rn(v.z - __bfloat162float(h2));
        __nv_bfloat16 l3 = __float2bfloat16_rn(v.w - __bfloat162float(h3));
        __nv_bfloat162 ph0 = __halves2bfloat162(h0, h1);
        __nv_bfloat162 ph1 = __halves2bfloat162(h2, h3);
        __nv_bfloat162 pl0 = __halves2bfloat162(l0, l1);
        __nv_bfloat162 pl1 = __halves2bfloat162(l2, l3);
        uint2 uh = make_uint2(*reinterpret_cast<uint32_t*>(&ph0),
                              *reinterpret_cast<uint32_t*>(&ph1));
        uint2 ul = make_uint2(*reinterpret_cast<uint32_t*>(&pl0),
                              *reinterpret_cast<uint32_t*>(&pl1));
        *reinterpret_cast<uint2*>(hi + i * 4) = uh;
        *reinterpret_cast<uint2*>(lo + i * 4) = ul;
    }
}

// ---------------------------------------------------------------------------
// Pure-plane GEMM. EPI: 0 = fp32 C (scale), 1 = GEMM1 epilogue (bias, planes).
// ---------------------------------------------------------------------------
template <int EPI>
__global__ __launch_bounds__(256, 2) void mma_gemm(
    const __nv_bfloat16* __restrict__ Ah, const __nv_bfloat16* __restrict__ Al,
    const __nv_bfloat16* __restrict__ Bh, const __nv_bfloat16* __restrict__ Bl,
    const float* __restrict__ bias, float* __restrict__ C,
    __nv_bfloat16* __restrict__ qkh, __nv_bfloat16* __restrict__ qkl,
    __nv_bfloat16* __restrict__ vth, __nv_bfloat16* __restrict__ vtl,
    int K, int lda, int ldb, int ldc,
    long sA, long sB, long sC, float scale)
{
    extern __shared__ char ds[];
    const int tid  = threadIdx.x;
    const int wid  = tid >> 5;
    const int lane = tid & 31;
    const int bm   = blockIdx.y * 128;
    const int bn   = blockIdx.x * 128;
    const int z    = blockIdx.z;

    Ah += z * sA + (long)bm * lda;  Al += z * sA + (long)bm * lda;
    Bh += z * sB + (long)bn * ldb;  Bl += z * sB + (long)bn * ldb;

    const int wm = (wid >> 2) << 6;
    const int wn = (wid & 3) << 5;

    float acc[4][4][4];
#pragma unroll
    for (int a = 0; a < 4; a++)
#pragma unroll
        for (int b = 0; b < 4; b++)
#pragma unroll
            for (int c = 0; c < 4; c++) acc[a][b][c] = 0.0f;

    const int nck = K >> 5;
    const uint32_t sb0 = smem_u32(ds);

    auto issue = [&](int ck) {
        const int k0 = ck << 5;
        const uint32_t sbase = sb0 + (ck % STAGES) * BUF;
#pragma unroll
        for (int t = 0; t < 4; t++) {
            const int i = tid + t * 256;
            const int pl = i >> 9, j = i & 511, r = j >> 2, cc = j & 3;
            const __nv_bfloat16* srcA = (pl ? Al : Ah) + (long)r * lda + k0 + cc * 8;
            cp_async16(sbase + r * 128 + (((cc + (pl ? 4 : 0)) ^ (r & 7)) << 4), srcA);
        }
#pragma unroll
        for (int t = 0; t < 4; t++) {
            const int i = tid + t * 256;
            const int pl = i >> 9, j = i & 511, r = j >> 2, cc = j & 3;
            const __nv_bfloat16* srcB = (pl ? Bl : Bh) + (long)r * ldb + k0 + cc * 8;
            cp_async16(sbase + 16384 + r * 128 + (((cc + (pl ? 4 : 0)) ^ (r & 7)) << 4), srcB);
        }
        cp_commit();
    };

    issue(0);
    if (nck > 1) issue(1);

    const int j = lane >> 3;
    const int arow = ((j & 1) << 3) | (lane & 7);
    const int acnk = j >> 1;
    const int brow = ((j >> 1) << 3) | (lane & 7);
    const int bcnk = j & 1;
    const int r7a = arow & 7;
    const int r7b = brow & 7;

    for (int ck = 0; ck < nck; ck++) {
        cp_wait<STAGES - 2>();
        __syncthreads();
        if (ck + 2 < nck) issue(ck + 2);

        const uint32_t bfA = sb0 + (ck % STAGES) * BUF;
        const uint32_t bfB = bfA + 16384;
#pragma unroll
        for (int s = 0; s < 2; s++) {
            const int c0 = s * 2;
            uint32_t ah[4][4], al[4][4], bh[2][4], bl[2][4];
#pragma unroll
            for (int mt = 0; mt < 4; mt++) {
                const int r = wm + (mt << 4) + arow;
                const uint32_t rb = bfA + r * 128;
                ldsm4(ah[mt], rb + (((c0 + acnk) ^ r7a) << 4));
                ldsm4(al[mt], rb + (((c0 + acnk + 4) ^ r7a) << 4));
            }
#pragma unroll
            for (int nt2 = 0; nt2 < 2; nt2++) {
                const int r = wn + (nt2 << 4) + brow;
                const uint32_t rb = bfB + r * 128;
                ldsm4(bh[nt2], rb + (((c0 + bcnk) ^ r7b) << 4));
                ldsm4(bl[nt2], rb + (((c0 + bcnk + 4) ^ r7b) << 4));
            }
#pragma unroll
            for (int mt = 0; mt < 4; mt++)
#pragma unroll
                for (int nt = 0; nt < 4; nt++) {
                    const int g = nt >> 1, q = (nt & 1) << 1;
                    hmma(acc[mt][nt], ah[mt], bh[g][q], bh[g][q + 1]);
                    hmma(acc[mt][nt], ah[mt], bl[g][q], bl[g][q + 1]);
                    hmma(acc[mt][nt], al[mt], bh[g][q], bh[g][q + 1]);
                }
        }
        __syncthreads();
    }

    // ---- epilogue
    const int mrow = lane >> 2;
    const int ncol = (lane & 3) << 1;
    if (EPI == 0) {
        float* Cz = C + (long)z * sC;
#pragma unroll
        for (int mt = 0; mt < 4; mt++) {
            const int m = bm + wm + (mt << 4) + mrow;
#pragma unroll
            for (int nt = 0; nt < 4; nt++) {
                const int n = bn + wn + (nt << 3) + ncol;
                float2 v0 = make_float2(acc[mt][nt][0] * scale, acc[mt][nt][1] * scale);
                float2 v1 = make_float2(acc[mt][nt][2] * scale, acc[mt][nt][3] * scale);
                *reinterpret_cast<float2*>(Cz + (long)m * ldc + n) = v0;
                *reinterpret_cast<float2*>(Cz + (long)(m + 8) * ldc + n) = v1;
            }
        }
    } else {
#pragma unroll
        for (int mt = 0; mt < 4; mt++) {
            const int m0 = bm + wm + (mt << 4) + mrow;
            const int m1 = m0 + 8;
#pragma unroll
            for (int nt = 0; nt < 4; nt++) {
                const int n = bn + wn + (nt << 3) + ncol;
                const float b0 = bias[n], b1 = bias[n + 1];
                float v00 = acc[mt][nt][0] + b0, v01 = acc[mt][nt][1] + b1;
                float v10 = acc[mt][nt][2] + b0, v11 = acc[mt][nt][3] + b1;
                __nv_bfloat16 h00 = __float2bfloat16_rn(v00);
                __nv_bfloat16 h01 = __float2bfloat16_rn(v01);
                __nv_bfloat16 h10 = __float2bfloat16_rn(v10);
                __nv_bfloat16 h11 = __float2bfloat16_rn(v11);
                __nv_bfloat16 l00 = __float2bfloat16_rn(v00 - __bfloat162float(h00));
                __nv_bfloat16 l01 = __float2bfloat16_rn(v01 - __bfloat162float(h01));
                __nv_bfloat16 l10 = __float2bfloat16_rn(v10 - __bfloat162float(h10));
                __nv_bfloat16 l11 = __float2bfloat16_rn(v11 - __bfloat162float(h11));
                if (n < 2048) {
                    __nv_bfloat162 ph0 = __halves2bfloat162(h00, h01);
                    __nv_bfloat162 pl0 = __halves2bfloat162(l00, l01);
                    __nv_bfloat162 ph1 = __halves2bfloat162(h10, h11);
                    __nv_bfloat162 pl1 = __halves2bfloat162(l10, l11);
                    *reinterpret_cast<__nv_bfloat162*>(&qkh[(long)m0 * 2048 + n]) = ph0;
                    *reinterpret_cast<__nv_bfloat162*>(&qkl[(long)m0 * 2048 + n]) = pl0;
                    *reinterpret_cast<__nv_bfloat162*>(&qkh[(long)m1 * 2048 + n]) = ph1;
                    *reinterpret_cast<__nv_bfloat162*>(&qkl[(long)m1 * 2048 + n]) = pl1;
                } else {
                    const int d = n - 2048;
                    const int bi0 = m0 >> 11, s0 = m0 & 2047;
                    const int bi1 = m1 >> 11, s1 = m1 & 2047;
                    __nv_bfloat16* th0 = vth + (long)bi0 * DIM * SEQ + (long)d * SEQ + s0;
                    __nv_bfloat16* tl0 = vtl + (long)bi0 * DIM * SEQ + (long)d * SEQ + s0;
                    __nv_bfloat16* th1 = vth + (long)bi1 * DIM * SEQ + (long)d * SEQ + s1;
                    __nv_bfloat16* tl1 = vtl + (long)bi1 * DIM * SEQ + (long)d * SEQ + s1;
                    th0[0] = h00; th0[SEQ] = h01; tl0[0] = l00; tl0[SEQ] = l01;
                    th1[0] = h10; th1[SEQ] = h11; tl1[0] = l10; tl1[SEQ] = l11;
                }
            }
        }
    }
}

// ---------------------------------------------------------------------------
// softmax + emit w planes
// ---------------------------------------------------------------------------
__global__ __launch_bounds__(256) void softmax_rows_kernel(
    float* __restrict__ w,
    __nv_bfloat16* __restrict__ wph, __nv_bfloat16* __restrict__ wpl)
{
    float* p = w + (long)blockIdx.x * SEQ;
    const int tid  = threadIdx.x;
    const int lane = tid & 31;
    const int warp = tid >> 5;

    float4 v0 = *reinterpret_cast<const float4*>(&p[tid * 4]);
    float4 v1 = *reinterpret_cast<const float4*>(&p[tid * 4 + 1024]);

    float m = fmaxf(fmaxf(fmaxf(v0.x, v0.y), fmaxf(v0.z, v0.w)),
                    fmaxf(fmaxf(v1.x, v1.y), fmaxf(v1.z, v1.w)));
    __shared__ float red[8];
#pragma unroll
    for (int o = 16; o; o >>= 1) m = fmaxf(m, __shfl_xor_sync(0xffffffffu, m, o));
    if (lane == 0) red[warp] = m;
    __syncthreads();
    float rmax = red[0];
#pragma unroll
    for (int i = 1; i < 8; i++) rmax = fmaxf(rmax, red[i]);
    __syncthreads();

    v0.x = __expf(v0.x - rmax); v0.y = __expf(v0.y - rmax);
    v0.z = __expf(v0.z - rmax); v0.w = __expf(v0.w - rmax);
    v1.x = __expf(v1.x - rmax); v1.y = __expf(v1.y - rmax);
    v1.z = __expf(v1.z - rmax); v1.w = __expf(v1.w - rmax);
    float s = v0.x + v0.y + v0.z + v0.w + v1.x + v1.y + v1.z + v1.w;
#pragma unroll
    for (int o = 16; o; o >>= 1) s += __shfl_xor_sync(0xffffffffu, s, o);
    if (lane == 0) red[warp] = s;
    __syncthreads();
    float tot = 0.0f;
#pragma unroll
    for (int i = 0; i < 8; i++) tot += red[i];
    const float inv = 1.0f / tot;

    v0.x *= inv; v0.y *= inv; v0.z *= inv; v0.w *= inv;
    v1.x *= inv; v1.y *= inv; v1.z *= inv; v1.w *= inv;
    *reinterpret_cast<float4*>(&p[tid * 4])        = v0;
    *reinterpret_cast<float4*>(&p[tid * 4 + 1024]) = v1;

    // emit hi/lo planes
    __nv_bfloat16* ph = wph + (long)blockIdx.x * SEQ;
    __nv_bfloat16* pl = wpl + (long)blockIdx.x * SEQ;
#pragma unroll
    for (int half = 0; half < 2; half++) {
        float4 v = half ? v1 : v0;
        const int off = tid * 4 + half * 1024;
        __nv_bfloat16 h0 = __float2bfloat16_rn(v.x);
        __nv_bfloat16 h1 = __float2bfloat16_rn(v.y);
        __nv_bfloat16 h2 = __float2bfloat16_rn(v.z);
        __nv_bfloat16 h3 = __float2bfloat16_rn(v.w);
        __nv_bfloat16 l0 = __float2bfloat16_rn(v.x - __bfloat162float(h0));
        __nv_bfloat16 l1 = __float2bfloat16_rn(v.y - __bfloat162float(h1));
        __nv_bfloat16 l2 = __float2bfloat16_rn(v.z - __bfloat162float(h2));
        __nv_bfloat16 l3 = __float2bfloat16_rn(v.w - __bfloat162float(h3));
        __nv_bfloat162 ph0 = __halves2bfloat162(h0, h1);
        __nv_bfloat162 ph1 = __halves2bfloat162(h2, h3);
        __nv_bfloat162 pl0 = __halves2bfloat162(l0, l1);
        __nv_bfloat162 pl1 = __halves2bfloat162(l2, l3);
        uint2 uh = make_uint2(*reinterpret_cast<uint32_t*>(&ph0),
                              *reinterpret_cast<uint32_t*>(&ph1));
        uint2 ul = make_uint2(*reinterpret_cast<uint32_t*>(&pl0),
                              *reinterpret_cast<uint32_t*>(&pl1));
        *reinterpret_cast<uint2*>(ph + off) = uh;
        *reinterpret_cast<uint2*>(pl + off) = ul;
    }
}

// ---------------------------------------------------------------------------
extern "C" void kernel_launch(void* const* d_in, const int* in_sizes, int n_in,
                              void* d_out, int out_size)
{
    const float* x  = (const float*)d_in[0];
    const float* Wq = (const float*)d_in[1];
    const float* bq = (const float*)d_in[2];

    float* out_attn = (float*)d_out;
    float* out_w    = out_attn + (long)ROWS * DIM;

    __nv_bfloat16 *xh, *xl, *wh, *wl, *qkh, *qkl, *vth, *vtl, *wph, *wpl;
    cudaGetSymbolAddress((void**)&xh, g_xh);
    cudaGetSymbolAddress((void**)&xl, g_xl);
    cudaGetSymbolAddress((void**)&wh, g_wh);
    cudaGetSymbolAddress((void**)&wl, g_wl);
    cudaGetSymbolAddress((void**)&qkh, g_qkh);
    cudaGetSymbolAddress((void**)&qkl, g_qkl);
    cudaGetSymbolAddress((void**)&vth, g_vth);
    cudaGetSymbolAddress((void**)&vtl, g_vtl);
    cudaGetSymbolAddress((void**)&wph, g_wph);
    cudaGetSymbolAddress((void**)&wpl, g_wpl);

    cudaFuncSetAttribute(mma_gemm<0>,
                         cudaFuncAttributeMaxDynamicSharedMemorySize, SMEM_TOTAL);
    cudaFuncSetAttribute(mma_gemm<1>,
                         cudaFuncAttributeMaxDynamicSharedMemorySize, SMEM_TOTAL);

    // 0) prepass: split x and W into planes
    split_planes<<<592, 256>>>(x, xh, xl, (long)ROWS * DIM / 4);
    split_planes<<<296, 256>>>(Wq, wh, wl, (long)3 * DIM * DIM / 4);

    // 1) qkv = x @ W^T + b : M=8192, N=3072, K=1024 -> qk planes + v^T planes
    mma_gemm<1><<<dim3(24, 64, 1), 256, SMEM_TOTAL>>>(
        xh, xl, wh, wl, bq, nullptr,
        qkh, qkl, vth, vtl,
        1024, 1024, 1024, 0, 0, 0, 0, 1.0f);

    // 2) scores = Q @ K^T / 32 : M=N=2048, K=1024, batched -> fp32 w region
    mma_gemm<0><<<dim3(16, 16, BATCH), 256, SMEM_TOTAL>>>(
        qkh, qkl, qkh + 1024, qkl + 1024, nullptr, out_w,
        nullptr, nullptr, nullptr, nullptr,
        1024, 2048, 2048, 2048,
        (long)SEQ * 2048, (long)SEQ * 2048, (long)SEQ * SEQ, 1.0f / 32.0f);

    // 3) softmax rows in place + emit w planes
    softmax_rows_kernel<<<ROWS, 256>>>(out_w, wph, wpl);

    // 4) out = w @ V : M=2048, N=1024, K=2048, batched
    mma_gemm<0><<<dim3(8, 16, BATCH), 256, SMEM_TOTAL>>>(
        wph, wpl, vth, vtl, nullptr, out_attn,
        nullptr, nullptr, nullptr, nullptr,
        2048, 2048, 2048, 1024,
        (long)SEQ * SEQ, (long)DIM * SEQ, (long)SEQ * DIM, 1.0f);
}

// round 6
// speedup vs baseline: 3.1255x; 1.0021x over previous
#include <cuda_runtime.h>
#include <cuda_bf16.h>
#include <cstdint>

// ---------------------------------------------------------------------------
// MaskedAttention, persistent bf16 hi/lo plane mma.sync GEMMs.
// prepass: x,W -> planes. GEMM1 -> qk planes + v^T planes (bias fused).
// GEMM2 -> fp32 scores. softmax -> fp32 w (output) + w planes.
// GEMM4 -> fp32 out. C[m,n] = scale * sum_k A[m,k]*B[n,k].
// ---------------------------------------------------------------------------

#define BATCH 4
#define SEQ   2048
#define DIM   1024
#define ROWS  (BATCH * SEQ)      // 8192

__device__ __nv_bfloat16 g_xh[(long)ROWS * DIM];
__device__ __nv_bfloat16 g_xl[(long)ROWS * DIM];
__device__ __nv_bfloat16 g_wh[(long)3 * DIM * DIM];
__device__ __nv_bfloat16 g_wl[(long)3 * DIM * DIM];
__device__ __nv_bfloat16 g_qkh[(long)ROWS * 2048];
__device__ __nv_bfloat16 g_qkl[(long)ROWS * 2048];
__device__ __nv_bfloat16 g_vth[(long)BATCH * DIM * SEQ];
__device__ __nv_bfloat16 g_vtl[(long)BATCH * DIM * SEQ];
__device__ __nv_bfloat16 g_wph[(long)ROWS * SEQ];
__device__ __nv_bfloat16 g_wpl[(long)ROWS * SEQ];

#define STAGES 3
#define BUF 32768
#define SMEM_TOTAL (STAGES * BUF)
#define PGRID 296                 // 2 CTAs per SM x 148 SMs

__device__ __forceinline__ uint32_t smem_u32(const void* p) {
    uint32_t a;
    asm("{ .reg .u64 t; cvta.to.shared.u64 t, %1; cvt.u32.u64 %0, t; }"
        : "=r"(a) : "l"(p));
    return a;
}
__device__ __forceinline__ void cp_async16(uint32_t s, const void* g) {
    asm volatile("cp.async.cg.shared.global [%0], [%1], 16;" :: "r"(s), "l"(g));
}
__device__ __forceinline__ void cp_commit() {
    asm volatile("cp.async.commit_group;" ::: "memory");
}
template <int N>
__device__ __forceinline__ void cp_wait() {
    asm volatile("cp.async.wait_group %0;" :: "n"(N) : "memory");
}
__device__ __forceinline__ void ldsm4(uint32_t* r, uint32_t addr) {
    asm volatile("ldmatrix.sync.aligned.m8n8.x4.shared.b16 {%0,%1,%2,%3}, [%4];"
                 : "=r"(r[0]), "=r"(r[1]), "=r"(r[2]), "=r"(r[3]) : "r"(addr));
}
__device__ __forceinline__ void hmma(float* c, const uint32_t* a, uint32_t b0, uint32_t b1) {
    asm volatile(
        "mma.sync.aligned.m16n8k16.row.col.f32.bf16.bf16.f32 "
        "{%0,%1,%2,%3}, {%4,%5,%6,%7}, {%8,%9}, {%0,%1,%2,%3};"
        : "+f"(c[0]), "+f"(c[1]), "+f"(c[2]), "+f"(c[3])
        : "r"(a[0]), "r"(a[1]), "r"(a[2]), "r"(a[3]), "r"(b0), "r"(b1));
}

// ---------------------------------------------------------------------------
__global__ __launch_bounds__(256) void split_planes(
    const float* __restrict__ src,
    __nv_bfloat16* __restrict__ hi, __nv_bfloat16* __restrict__ lo, long n4)
{
    for (long i = blockIdx.x * 256 + threadIdx.x; i < n4; i += (long)gridDim.x * 256) {
        float4 v = *reinterpret_cast<const float4*>(src + i * 4);
        __nv_bfloat16 h0 = __float2bfloat16_rn(v.x);
        __nv_bfloat16 h1 = __float2bfloat16_rn(v.y);
        __nv_bfloat16 h2 = __float2bfloat16_rn(v.z);
        __nv_bfloat16 h3 = __float2bfloat16_rn(v.w);
        __nv_bfloat16 l0 = __float2bfloat16_rn(v.x - __bfloat162float(h0));
        __nv_bfloat16 l1 = __float2bfloat16_rn(v.y - __bfloat162float(h1));
        __nv_bfloat16 l2 = __float2bfloat16_rn(v.z - __bfloat162float(h2));
        __nv_bfloat16 l3 = __float2bfloat16_rn(v.w - __bfloat162float(h3));
        __nv_bfloat162 ph0 = __halves2bfloat162(h0, h1);
        __nv_bfloat162 ph1 = __halves2bfloat162(h2, h3);
        __nv_bfloat162 pl0 = __halves2bfloat162(l0, l1);
        __nv_bfloat162 pl1 = __halves2bfloat162(l2, l3);
        uint2 uh = make_uint2(*reinterpret_cast<uint32_t*>(&ph0),
                              *reinterpret_cast<uint32_t*>(&ph1));
        uint2 ul = make_uint2(*reinterpret_cast<uint32_t*>(&pl0),
                              *reinterpret_cast<uint32_t*>(&pl1));
        *reinterpret_cast<uint2*>(hi + i * 4) = uh;
        *reinterpret_cast<uint2*>(lo + i * 4) = ul;
    }
}

// ---------------------------------------------------------------------------
// Persistent pure-plane GEMM. EPI: 0 = fp32 C, 1 = GEMM1 epilogue.
// ---------------------------------------------------------------------------
template <int EPI>
__global__ __launch_bounds__(256, 2) void mma_gemm(
    const __nv_bfloat16* __restrict__ Ah0, const __nv_bfloat16* __restrict__ Al0,
    const __nv_bfloat16* __restrict__ Bh0, const __nv_bfloat16* __restrict__ Bl0,
    const float* __restrict__ bias, float* __restrict__ C,
    __nv_bfloat16* __restrict__ qkh, __nv_bfloat16* __restrict__ qkl,
    __nv_bfloat16* __restrict__ vth, __nv_bfloat16* __restrict__ vtl,
    int K, int lda, int ldb, int ldc,
    long sA, long sB, long sC, float scale,
    int nbx, int nby, int nz)
{
    extern __shared__ char ds[];
    const int tid  = threadIdx.x;
    const int wid  = tid >> 5;
    const int lane = tid & 31;
    const int wm = (wid >> 2) << 6;
    const int wn = (wid & 3) << 5;

    const uint32_t sb0 = smem_u32(ds);
    const int nck   = K >> 5;
    const int per_z = nbx * nby;
    const int total = per_z * nz;
    const int gw    = nbx * 8;

    auto tile_ptrs = [&](int t,
                         const __nv_bfloat16*& Ah, const __nv_bfloat16*& Al,
                         const __nv_bfloat16*& Bh, const __nv_bfloat16*& Bl,
                         int& bm, int& bn, int& z) {
        z = t / per_z;
        int r = t - z * per_z;
        int g = r / gw, rr = r - g * gw;
        bm = (g * 8 + (rr & 7)) * 128;
        bn = (rr >> 3) * 128;
        long ao = (long)z * sA + (long)bm * lda;
        long bo = (long)z * sB + (long)bn * ldb;
        Ah = Ah0 + ao; Al = Al0 + ao; Bh = Bh0 + bo; Bl = Bl0 + bo;
    };

    auto issue = [&](const __nv_bfloat16* Ah, const __nv_bfloat16* Al,
                     const __nv_bfloat16* Bh, const __nv_bfloat16* Bl,
                     int k0, uint32_t sbase) {
#pragma unroll
        for (int tt = 0; tt < 4; tt++) {
            const int i = tid + tt * 256;
            const int pl = i >> 9, j2 = i & 511, r = j2 >> 2, cc = j2 & 3;
            const __nv_bfloat16* src = (pl ? Al : Ah) + (long)r * lda + k0 + cc * 8;
            cp_async16(sbase + r * 128 + (((cc + (pl ? 4 : 0)) ^ (r & 7)) << 4), src);
        }
#pragma unroll
        for (int tt = 0; tt < 4; tt++) {
            const int i = tid + tt * 256;
            const int pl = i >> 9, j2 = i & 511, r = j2 >> 2, cc = j2 & 3;
            const __nv_bfloat16* src = (pl ? Bl : Bh) + (long)r * ldb + k0 + cc * 8;
            cp_async16(sbase + 16384 + r * 128 + (((cc + (pl ? 4 : 0)) ^ (r & 7)) << 4), src);
        }
        cp_commit();
    };

    // ldsm per-lane constants
    const int j = lane >> 3;
    const int arow = ((j & 1) << 3) | (lane & 7);
    const int acnk = j >> 1;
    const int brow = ((j >> 1) << 3) | (lane & 7);
    const int bcnk = j & 1;
    const int r7a = arow & 7;
    const int r7b = brow & 7;

    int t = blockIdx.x;
    if (t >= total) return;
    const __nv_bfloat16 *cAh, *cAl, *cBh, *cBl;
    int bm, bn, z;
    tile_ptrs(t, cAh, cAl, cBh, cBl, bm, bn, z);
    issue(cAh, cAl, cBh, cBl, 0, sb0);
    issue(cAh, cAl, cBh, cBl, 32, sb0 + BUF);
    int cs = 0;

    while (true) {
        float acc[4][4][4];
#pragma unroll
        for (int a = 0; a < 4; a++)
#pragma unroll
            for (int b = 0; b < 4; b++)
#pragma unroll
                for (int c = 0; c < 4; c++) acc[a][b][c] = 0.0f;

        const int tn = t + gridDim.x;
        const bool hn = tn < total;
        const __nv_bfloat16 *nAh, *nAl, *nBh, *nBl;
        int nbm, nbn, nz2;
        if (hn) tile_ptrs(tn, nAh, nAl, nBh, nBl, nbm, nbn, nz2);

        for (int ck = 0; ck < nck; ck++) {
            cp_wait<STAGES - 2>();
            __syncthreads();
            const int fs = (cs == 0) ? 2 : cs - 1;        // (cs+2)%3
            const uint32_t fb = sb0 + fs * BUF;
            if (ck + 2 < nck)       issue(cAh, cAl, cBh, cBl, (ck + 2) << 5, fb);
            else if (hn)            issue(nAh, nAl, nBh, nBl, (ck + 2 - nck) << 5, fb);
            else                    cp_commit();

            const uint32_t bfA = sb0 + cs * BUF;
            const uint32_t bfB = bfA + 16384;
#pragma unroll
            for (int s = 0; s < 2; s++) {
                const int c0 = s * 2;
                uint32_t ah[4][4], al[4][4], bh[2][4], bl[2][4];
#pragma unroll
                for (int mt = 0; mt < 4; mt++) {
                    const int r = wm + (mt << 4) + arow;
                    const uint32_t rb = bfA + r * 128;
                    ldsm4(ah[mt], rb + (((c0 + acnk) ^ r7a) << 4));
                    ldsm4(al[mt], rb + (((c0 + acnk + 4) ^ r7a) << 4));
                }
#pragma unroll
                for (int nt2 = 0; nt2 < 2; nt2++) {
                    const int r = wn + (nt2 << 4) + brow;
                    const uint32_t rb = bfB + r * 128;
                    ldsm4(bh[nt2], rb + (((c0 + bcnk) ^ r7b) << 4));
                    ldsm4(bl[nt2], rb + (((c0 + bcnk + 4) ^ r7b) << 4));
                }
#pragma unroll
                for (int mt = 0; mt < 4; mt++)
#pragma unroll
                    for (int nt = 0; nt < 4; nt++) {
                        const int g = nt >> 1, q = (nt & 1) << 1;
                        hmma(acc[mt][nt], ah[mt], bh[g][q], bh[g][q + 1]);
                        hmma(acc[mt][nt], ah[mt], bl[g][q], bl[g][q + 1]);
                        hmma(acc[mt][nt], al[mt], bh[g][q], bh[g][q + 1]);
                    }
            }
            cs = (cs == 2) ? 0 : cs + 1;
        }

        // ---- epilogue (register-only; overlaps next tile's cp.async)
        const int mrow = lane >> 2;
        const int ncol = (lane & 3) << 1;
        if (EPI == 0) {
            float* Cz = C + (long)z * sC;
#pragma unroll
            for (int mt = 0; mt < 4; mt++) {
                const int m = bm + wm + (mt << 4) + mrow;
#pragma unroll
                for (int nt = 0; nt < 4; nt++) {
                    const int n = bn + wn + (nt << 3) + ncol;
                    float2 v0 = make_float2(acc[mt][nt][0] * scale, acc[mt][nt][1] * scale);
                    float2 v1 = make_float2(acc[mt][nt][2] * scale, acc[mt][nt][3] * scale);
                    *reinterpret_cast<float2*>(Cz + (long)m * ldc + n) = v0;
                    *reinterpret_cast<float2*>(Cz + (long)(m + 8) * ldc + n) = v1;
                }
            }
        } else {
#pragma unroll
            for (int mt = 0; mt < 4; mt++) {
                const int m0 = bm + wm + (mt << 4) + mrow;
                const int m1 = m0 + 8;
#pragma unroll
                for (int nt = 0; nt < 4; nt++) {
                    const int n = bn + wn + (nt << 3) + ncol;
                    const float b0 = bias[n], b1 = bias[n + 1];
                    float v00 = acc[mt][nt][0] + b0, v01 = acc[mt][nt][1] + b1;
                    float v10 = acc[mt][nt][2] + b0, v11 = acc[mt][nt][3] + b1;
                    __nv_bfloat16 h00 = __float2bfloat16_rn(v00);
                    __nv_bfloat16 h01 = __float2bfloat16_rn(v01);
                    __nv_bfloat16 h10 = __float2bfloat16_rn(v10);
                    __nv_bfloat16 h11 = __float2bfloat16_rn(v11);
                    __nv_bfloat16 l00 = __float2bfloat16_rn(v00 - __bfloat162float(h00));
                    __nv_bfloat16 l01 = __float2bfloat16_rn(v01 - __bfloat162float(h01));
                    __nv_bfloat16 l10 = __float2bfloat16_rn(v10 - __bfloat162float(h10));
                    __nv_bfloat16 l11 = __float2bfloat16_rn(v11 - __bfloat162float(h11));
                    if (n < 2048) {
                        __nv_bfloat162 ph0 = __halves2bfloat162(h00, h01);
                        __nv_bfloat162 pl0 = __halves2bfloat162(l00, l01);
                        __nv_bfloat162 ph1 = __halves2bfloat162(h10, h11);
                        __nv_bfloat162 pl1 = __halves2bfloat162(l10, l11);
                        *reinterpret_cast<__nv_bfloat162*>(&qkh[(long)m0 * 2048 + n]) = ph0;
                        *reinterpret_cast<__nv_bfloat162*>(&qkl[(long)m0 * 2048 + n]) = pl0;
                        *reinterpret_cast<__nv_bfloat162*>(&qkh[(long)m1 * 2048 + n]) = ph1;
                        *reinterpret_cast<__nv_bfloat162*>(&qkl[(long)m1 * 2048 + n]) = pl1;
                    } else {
                        const int d = n - 2048;
                        const int bi0 = m0 >> 11, s0 = m0 & 2047;
                        const int bi1 = m1 >> 11, s1 = m1 & 2047;
                        __nv_bfloat16* th0 = vth + (long)bi0 * DIM * SEQ + (long)d * SEQ + s0;
                        __nv_bfloat16* tl0 = vtl + (long)bi0 * DIM * SEQ + (long)d * SEQ + s0;
                        __nv_bfloat16* th1 = vth + (long)bi1 * DIM * SEQ + (long)d * SEQ + s1;
                        __nv_bfloat16* tl1 = vtl + (long)bi1 * DIM * SEQ + (long)d * SEQ + s1;
                        th0[0] = h00; th0[SEQ] = h01; tl0[0] = l00; tl0[SEQ] = l01;
                        th1[0] = h10; th1[SEQ] = h11; tl1[0] = l10; tl1[SEQ] = l11;
                    }
                }
            }
        }

        if (!hn) break;
        t = tn;
        cAh = nAh; cAl = nAl; cBh = nBh; cBl = nBl;
        bm = nbm; bn = nbn; z = nz2;
    }
}

// ---------------------------------------------------------------------------
__global__ __launch_bounds__(256) void softmax_rows_kernel(
    float* __restrict__ w,
    __nv_bfloat16* __restrict__ wph, __nv_bfloat16* __restrict__ wpl)
{
    float* p = w + (long)blockIdx.x * SEQ;
    const int tid  = threadIdx.x;
    const int lane = tid & 31;
    const int warp = tid >> 5;

    float4 v0 = *reinterpret_cast<const float4*>(&p[tid * 4]);
    float4 v1 = *reinterpret_cast<const float4*>(&p[tid * 4 + 1024]);

    float m = fmaxf(fmaxf(fmaxf(v0.x, v0.y), fmaxf(v0.z, v0.w)),
                    fmaxf(fmaxf(v1.x, v1.y), fmaxf(v1.z, v1.w)));
    __shared__ float red[8];
#pragma unroll
    for (int o = 16; o; o >>= 1) m = fmaxf(m, __shfl_xor_sync(0xffffffffu, m, o));
    if (lane == 0) red[warp] = m;
    __syncthreads();
    float rmax = red[0];
#pragma unroll
    for (int i = 1; i < 8; i++) rmax = fmaxf(rmax, red[i]);
    __syncthreads();

    v0.x = __expf(v0.x - rmax); v0.y = __expf(v0.y - rmax);
    v0.z = __expf(v0.z - rmax); v0.w = __expf(v0.w - rmax);
    v1.x = __expf(v1.x - rmax); v1.y = __expf(v1.y - rmax);
    v1.z = __expf(v1.z - rmax); v1.w = __expf(v1.w - rmax);
    float s = v0.x + v0.y + v0.z + v0.w + v1.x + v1.y + v1.z + v1.w;
#pragma unroll
    for (int o = 16; o; o >>= 1) s += __shfl_xor_sync(0xffffffffu, s, o);
    if (lane == 0) red[warp] = s;
    __syncthreads();
    float tot = 0.0f;
#pragma unroll
    for (int i = 0; i < 8; i++) tot += red[i];
    const float inv = 1.0f / tot;

    v0.x *= inv; v0.y *= inv; v0.z *= inv; v0.w *= inv;
    v1.x *= inv; v1.y *= inv; v1.z *= inv; v1.w *= inv;
    *reinterpret_cast<float4*>(&p[tid * 4])        = v0;
    *reinterpret_cast<float4*>(&p[tid * 4 + 1024]) = v1;

    __nv_bfloat16* ph = wph + (long)blockIdx.x * SEQ;
    __nv_bfloat16* pl = wpl + (long)blockIdx.x * SEQ;
#pragma unroll
    for (int half = 0; half < 2; half++) {
        float4 v = half ? v1 : v0;
        const int off = tid * 4 + half * 1024;
        __nv_bfloat16 h0 = __float2bfloat16_rn(v.x);
        __nv_bfloat16 h1 = __float2bfloat16_rn(v.y);
        __nv_bfloat16 h2 = __float2bfloat16_rn(v.z);
        __nv_bfloat16 h3 = __float2bfloat16_rn(v.w);
        __nv_bfloat16 l0 = __float2bfloat16_rn(v.x - __bfloat162float(h0));
        __nv_bfloat16 l1 = __float2bfloat16_rn(v.y - __bfloat162float(h1));
        __nv_bfloat16 l2 = __float2bfloat16_rn(v.z - __bfloat162float(h2));
        __nv_bfloat16 l3 = __float2bfloat16_rn(v.w - __bfloat162float(h3));
        __nv_bfloat162 ph0 = __halves2bfloat162(h0, h1);
        __nv_bfloat162 ph1 = __halves2bfloat162(h2, h3);
        __nv_bfloat162 pl0 = __halves2bfloat162(l0, l1);
        __nv_bfloat162 pl1 = __halves2bfloat162(l2, l3);
        uint2 uh = make_uint2(*reinterpret_cast<uint32_t*>(&ph0),
                              *reinterpret_cast<uint32_t*>(&ph1));
        uint2 ul = make_uint2(*reinterpret_cast<uint32_t*>(&pl0),
                              *reinterpret_cast<uint32_t*>(&pl1));
        *reinterpret_cast<uint2*>(ph + off) = uh;
        *reinterpret_cast<uint2*>(pl + off) = ul;
    }
}

// ---------------------------------------------------------------------------
extern "C" void kernel_launch(void* const* d_in, const int* in_sizes, int n_in,
                              void* d_out, int out_size)
{
    const float* x  = (const float*)d_in[0];
    const float* Wq = (const float*)d_in[1];
    const float* bq = (const float*)d_in[2];

    float* out_attn = (float*)d_out;
    float* out_w    = out_attn + (long)ROWS * DIM;

    __nv_bfloat16 *xh, *xl, *wh, *wl, *qkh, *qkl, *vth, *vtl, *wph, *wpl;
    cudaGetSymbolAddress((void**)&xh, g_xh);
    cudaGetSymbolAddress((void**)&xl, g_xl);
    cudaGetSymbolAddress((void**)&wh, g_wh);
    cudaGetSymbolAddress((void**)&wl, g_wl);
    cudaGetSymbolAddress((void**)&qkh, g_qkh);
    cudaGetSymbolAddress((void**)&qkl, g_qkl);
    cudaGetSymbolAddress((void**)&vth, g_vth);
    cudaGetSymbolAddress((void**)&vtl, g_vtl);
    cudaGetSymbolAddress((void**)&wph, g_wph);
    cudaGetSymbolAddress((void**)&wpl, g_wpl);

    cudaFuncSetAttribute(mma_gemm<0>,
                         cudaFuncAttributeMaxDynamicSharedMemorySize, SMEM_TOTAL);
    cudaFuncSetAttribute(mma_gemm<1>,
                         cudaFuncAttributeMaxDynamicSharedMemorySize, SMEM_TOTAL);

    // 0) prepass: split x and W into planes
    split_planes<<<592, 256>>>(x, xh, xl, (long)ROWS * DIM / 4);
    split_planes<<<296, 256>>>(Wq, wh, wl, (long)3 * DIM * DIM / 4);

    // 1) qkv = x @ W^T + b : M=8192, N=3072, K=1024 -> qk planes + v^T planes
    mma_gemm<1><<<PGRID, 256, SMEM_TOTAL>>>(
        xh, xl, wh, wl, bq, nullptr,
        qkh, qkl, vth, vtl,
        1024, 1024, 1024, 0, 0, 0, 0, 1.0f,
        24, 64, 1);

    // 2) scores = Q @ K^T / 32 : M=N=2048, K=1024, batched -> fp32 w region
    mma_gemm<0><<<PGRID, 256, SMEM_TOTAL>>>(
        qkh, qkl, qkh + 1024, qkl + 1024, nullptr, out_w,
        nullptr, nullptr, nullptr, nullptr,
        1024, 2048, 2048, 2048,
        (long)SEQ * 2048, (long)SEQ * 2048, (long)SEQ * SEQ, 1.0f / 32.0f,
        16, 16, BATCH);

    // 3) softmax rows in place + emit w planes
    softmax_rows_kernel<<<ROWS, 256>>>(out_w, wph, wpl);

    // 4) out = w @ V : M=2048, N=1024, K=2048, batched
    mma_gemm<0><<<PGRID, 256, SMEM_TOTAL>>>(
        wph, wpl, vth, vtl, nullptr, out_attn,
        nullptr, nullptr, nullptr, nullptr,
        2048, 2048, 2048, 1024,
        (long)SEQ * SEQ, (long)DIM * SEQ, (long)SEQ * DIM, 1.0f,
        8, 16, BATCH);
}

// round 7
// speedup vs baseline: 3.9717x; 1.2707x over previous
#include <cuda_runtime.h>
#include <cuda_fp16.h>
#include <cstdint>

// ---------------------------------------------------------------------------
// MaskedAttention via fp16 hi/lo plane mma.sync GEMMs.
// GEMM1 (3-term, exact-ish): qkv = x@W^T+b -> Q/K planes (hi+lo) + V^T planes.
// GEMM2 (2-term): scores = Qh·(Kh+Kl)/32. softmax -> w fp32 + w hi plane.
// GEMM4 (2-term): out = wh·(Vh+Vl).  All NT: C[m,n]=scale*sum_k A[m,k]B[n,k].
// ---------------------------------------------------------------------------

#define BATCH 4
#define SEQ   2048
#define DIM   1024
#define ROWS  (BATCH * SEQ)      // 8192

__device__ __half g_xh[(long)ROWS * DIM];
__device__ __half g_xl[(long)ROWS * DIM];
__device__ __half g_wh[(long)3 * DIM * DIM];
__device__ __half g_wl[(long)3 * DIM * DIM];
__device__ __half g_qkh[(long)ROWS * 2048];
__device__ __half g_qkl[(long)ROWS * 2048];
__device__ __half g_vth[(long)BATCH * DIM * SEQ];
__device__ __half g_vtl[(long)BATCH * DIM * SEQ];
__device__ __half g_wph[(long)ROWS * SEQ];

__device__ __forceinline__ uint32_t smem_u32(const void* p) {
    uint32_t a;
    asm("{ .reg .u64 t; cvta.to.shared.u64 t, %1; cvt.u32.u64 %0, t; }"
        : "=r"(a) : "l"(p));
    return a;
}
__device__ __forceinline__ void cp_async16(uint32_t s, const void* g) {
    asm volatile("cp.async.cg.shared.global [%0], [%1], 16;" :: "r"(s), "l"(g));
}
__device__ __forceinline__ void cp_commit() {
    asm volatile("cp.async.commit_group;" ::: "memory");
}
template <int N>
__device__ __forceinline__ void cp_wait() {
    asm volatile("cp.async.wait_group %0;" :: "n"(N) : "memory");
}
__device__ __forceinline__ void ldsm4(uint32_t* r, uint32_t addr) {
    asm volatile("ldmatrix.sync.aligned.m8n8.x4.shared.b16 {%0,%1,%2,%3}, [%4];"
                 : "=r"(r[0]), "=r"(r[1]), "=r"(r[2]), "=r"(r[3]) : "r"(addr));
}
__device__ __forceinline__ void hmma(float* c, const uint32_t* a, uint32_t b0, uint32_t b1) {
    asm volatile(
        "mma.sync.aligned.m16n8k16.row.col.f32.f16.f16.f32 "
        "{%0,%1,%2,%3}, {%4,%5,%6,%7}, {%8,%9}, {%0,%1,%2,%3};"
        : "+f"(c[0]), "+f"(c[1]), "+f"(c[2]), "+f"(c[3])
        : "r"(a[0]), "r"(a[1]), "r"(a[2]), "r"(a[3]), "r"(b0), "r"(b1));
}
__device__ __forceinline__ void split_h(float v, __half& h, __half& l) {
    h = __float2half_rn(v);
    l = __float2half_rn(v - __half2float(h));
}

// ---------------------------------------------------------------------------
__global__ __launch_bounds__(256) void split_planes(
    const float* __restrict__ src,
    __half* __restrict__ hi, __half* __restrict__ lo, long n4)
{
    for (long i = blockIdx.x * 256 + threadIdx.x; i < n4; i += (long)gridDim.x * 256) {
        float4 v = *reinterpret_cast<const float4*>(src + i * 4);
        __half h0, h1, h2, h3, l0, l1, l2, l3;
        split_h(v.x, h0, l0); split_h(v.y, h1, l1);
        split_h(v.z, h2, l2); split_h(v.w, h3, l3);
        __half2 a = __halves2half2(h0, h1), b = __halves2half2(h2, h3);
        __half2 c = __halves2half2(l0, l1), d = __halves2half2(l2, l3);
        uint2 uh = make_uint2(*reinterpret_cast<uint32_t*>(&a),
                              *reinterpret_cast<uint32_t*>(&b));
        uint2 ul = make_uint2(*reinterpret_cast<uint32_t*>(&c),
                              *reinterpret_cast<uint32_t*>(&d));
        *reinterpret_cast<uint2*>(hi + i * 4) = uh;
        *reinterpret_cast<uint2*>(lo + i * 4) = ul;
    }
}

// ---------------------------------------------------------------------------
// AT: 2 = A hi only (2 MMAs), 3 = A hi+lo (3 MMAs).
// EPI: 0 = fp32 C (scale), 1 = GEMM1 epilogue (bias, fp16 planes out).
// STG: pipeline stages.
// A tile: 64 phys rows x 128B (8KB/plane). B tile: 128 rows x 128B hi|lo 16KB.
// ---------------------------------------------------------------------------
template <int AT, int EPI, int STG>
__global__ __launch_bounds__(256, 2) void mma_gemm(
    const __half* __restrict__ Ah, const __half* __restrict__ Al,
    const __half* __restrict__ Bh, const __half* __restrict__ Bl,
    const float* __restrict__ bias, float* __restrict__ C,
    __half* __restrict__ qkh, __half* __restrict__ qkl,
    __half* __restrict__ vth, __half* __restrict__ vtl,
    int K, int lda, int ldb, int ldc,
    long sA, long sB, long sC, float scale)
{
    constexpr int APL  = (AT == 3) ? 2 : 1;
    constexpr int OFFB = APL * 8192;
    constexpr int BUFS = OFFB + 16384;

    extern __shared__ char ds[];
    const int tid  = threadIdx.x;
    const int wid  = tid >> 5;
    const int lane = tid & 31;
    const int bm   = blockIdx.y * 128;
    const int bn   = blockIdx.x * 128;
    const int z    = blockIdx.z;

    Ah += z * sA + (long)bm * lda;
    if (AT == 3) Al += z * sA + (long)bm * lda;
    Bh += z * sB + (long)bn * ldb;
    Bl += z * sB + (long)bn * ldb;

    const int wm = (wid >> 2) << 6;     // 0 or 64
    const int wn = (wid & 3) << 5;      // 0,32,64,96

    float acc[4][4][4];
#pragma unroll
    for (int a = 0; a < 4; a++)
#pragma unroll
        for (int b = 0; b < 4; b++)
#pragma unroll
            for (int c = 0; c < 4; c++) acc[a][b][c] = 0.0f;

    const int nck = K >> 5;
    const uint32_t sb0 = smem_u32(ds);

    auto issue = [&](int ck) {
        const int k0 = ck << 5;
        const uint32_t sbase = sb0 + (ck % STG) * BUFS;
#pragma unroll
        for (int p = 0; p < APL; p++) {
#pragma unroll
            for (int t = 0; t < 2; t++) {
                const int i = tid + t * 256;          // 0..511
                const int r = i >> 2, c = i & 3;
                const __half* src = (p ? Al : Ah) + (long)r * lda + k0 + c * 8;
                const int pr = r & 63, cc = ((r >> 6) << 2) | c;
                cp_async16(sbase + p * 8192 + pr * 128 + ((cc ^ (pr & 7)) << 4), src);
            }
        }
#pragma unroll
        for (int t = 0; t < 4; t++) {
            const int i = tid + t * 256;              // 0..1023
            const int pl = i >> 9, j2 = i & 511, r = j2 >> 2, c = j2 & 3;
            const __half* src = (pl ? Bl : Bh) + (long)r * ldb + k0 + c * 8;
            cp_async16(sbase + OFFB + r * 128 + (((c + (pl ? 4 : 0)) ^ (r & 7)) << 4), src);
        }
        cp_commit();
    };

#pragma unroll
    for (int i = 0; i < STG - 1; i++) issue(i);

    // ldsm per-lane constants
    const int j = lane >> 3;
    const int arow = ((j & 1) << 3) | (lane & 7);
    const int acnk = j >> 1;
    const int brow = ((j >> 1) << 3) | (lane & 7);
    const int bcnk = j & 1;
    const int r7a = arow & 7;
    const int r7b = brow & 7;
    const int hiBit4 = (wm >> 6) << 2;   // A col-block select (0 or 4)

    for (int ck = 0; ck < nck; ck++) {
        cp_wait<STG - 2>();
        __syncthreads();
        if (ck + STG - 1 < nck) issue(ck + STG - 1);

        const uint32_t bfA = sb0 + (ck % STG) * BUFS;
        const uint32_t bfB = bfA + OFFB;
#pragma unroll
        for (int s = 0; s < 2; s++) {
            const int c0 = s * 2;
            uint32_t ah[4][4], al[4][4], bh[2][4], bl[2][4];
#pragma unroll
            for (int mt = 0; mt < 4; mt++) {
                const int pr = (mt << 4) + arow;      // 0..63
                const int cc = hiBit4 + c0 + acnk;
                const uint32_t ad = bfA + pr * 128 + ((cc ^ r7a) << 4);
                ldsm4(ah[mt], ad);
                if (AT == 3) ldsm4(al[mt], ad + 8192);
            }
#pragma unroll
            for (int nt2 = 0; nt2 < 2; nt2++) {
                const int r = wn + (nt2 << 4) + brow;
                const uint32_t rb = bfB + r * 128;
                ldsm4(bh[nt2], rb + (((c0 + bcnk) ^ r7b) << 4));
                ldsm4(bl[nt2], rb + (((c0 + bcnk + 4) ^ r7b) << 4));
            }
#pragma unroll
            for (int mt = 0; mt < 4; mt++)
#pragma unroll
                for (int nt = 0; nt < 4; nt++) {
                    const int g = nt >> 1, q = (nt & 1) << 1;
                    hmma(acc[mt][nt], ah[mt], bh[g][q], bh[g][q + 1]);
                    hmma(acc[mt][nt], ah[mt], bl[g][q], bl[g][q + 1]);
                    if (AT == 3) hmma(acc[mt][nt], al[mt], bh[g][q], bh[g][q + 1]);
                }
        }
    }

    // ---- epilogue
    const int mrow = lane >> 2;
    const int ncol = (lane & 3) << 1;
    if (EPI == 0) {
        float* Cz = C + (long)z * sC;
#pragma unroll
        for (int mt = 0; mt < 4; mt++) {
            const int m = bm + wm + (mt << 4) + mrow;
#pragma unroll
            for (int nt = 0; nt < 4; nt++) {
                const int n = bn + wn + (nt << 3) + ncol;
                float2 v0 = make_float2(acc[mt][nt][0] * scale, acc[mt][nt][1] * scale);
                float2 v1 = make_float2(acc[mt][nt][2] * scale, acc[mt][nt][3] * scale);
                *reinterpret_cast<float2*>(Cz + (long)m * ldc + n) = v0;
                *reinterpret_cast<float2*>(Cz + (long)(m + 8) * ldc + n) = v1;
            }
        }
    } else {
#pragma unroll
        for (int mt = 0; mt < 4; mt++) {
            const int m0 = bm + wm + (mt << 4) + mrow;
            const int m1 = m0 + 8;
#pragma unroll
            for (int nt = 0; nt < 4; nt++) {
                const int n = bn + wn + (nt << 3) + ncol;
                const float b0 = bias[n], b1 = bias[n + 1];
                float v00 = acc[mt][nt][0] + b0, v01 = acc[mt][nt][1] + b1;
                float v10 = acc[mt][nt][2] + b0, v11 = acc[mt][nt][3] + b1;
                __half h00, h01, h10, h11, l00, l01, l10, l11;
                split_h(v00, h00, l00); split_h(v01, h01, l01);
                split_h(v10, h10, l10); split_h(v11, h11, l11);
                if (n < 2048) {
                    __half2 ph0 = __halves2half2(h00, h01);
                    __half2 pl0 = __halves2half2(l00, l01);
                    __half2 ph1 = __halves2half2(h10, h11);
                    __half2 pl1 = __halves2half2(l10, l11);
                    *reinterpret_cast<__half2*>(&qkh[(long)m0 * 2048 + n]) = ph0;
                    *reinterpret_cast<__half2*>(&qkl[(long)m0 * 2048 + n]) = pl0;
                    *reinterpret_cast<__half2*>(&qkh[(long)m1 * 2048 + n]) = ph1;
                    *reinterpret_cast<__half2*>(&qkl[(long)m1 * 2048 + n]) = pl1;
                } else {
                    const int d = n - 2048;
                    const int bi0 = m0 >> 11, s0 = m0 & 2047;
                    const int bi1 = m1 >> 11, s1 = m1 & 2047;
                    __half* th0 = vth + (long)bi0 * DIM * SEQ + (long)d * SEQ + s0;
                    __half* tl0 = vtl + (long)bi0 * DIM * SEQ + (long)d * SEQ + s0;
                    __half* th1 = vth + (long)bi1 * DIM * SEQ + (long)d * SEQ + s1;
                    __half* tl1 = vtl + (long)bi1 * DIM * SEQ + (long)d * SEQ + s1;
                    th0[0] = h00; th0[SEQ] = h01; tl0[0] = l00; tl0[SEQ] = l01;
                    th1[0] = h10; th1[SEQ] = h11; tl1[0] = l10; tl1[SEQ] = l11;
                }
            }
        }
    }
}

// ---------------------------------------------------------------------------
// softmax + emit w hi plane only (A operand of GEMM4 needs hi only)
// ---------------------------------------------------------------------------
__global__ __launch_bounds__(256) void softmax_rows_kernel(
    float* __restrict__ w, __half* __restrict__ wph)
{
    float* p = w + (long)blockIdx.x * SEQ;
    const int tid  = threadIdx.x;
    const int lane = tid & 31;
    const int warp = tid >> 5;

    float4 v0 = *reinterpret_cast<const float4*>(&p[tid * 4]);
    float4 v1 = *reinterpret_cast<const float4*>(&p[tid * 4 + 1024]);

    float m = fmaxf(fmaxf(fmaxf(v0.x, v0.y), fmaxf(v0.z, v0.w)),
                    fmaxf(fmaxf(v1.x, v1.y), fmaxf(v1.z, v1.w)));
    __shared__ float red[8];
#pragma unroll
    for (int o = 16; o; o >>= 1) m = fmaxf(m, __shfl_xor_sync(0xffffffffu, m, o));
    if (lane == 0) red[warp] = m;
    __syncthreads();
    float rmax = red[0];
#pragma unroll
    for (int i = 1; i < 8; i++) rmax = fmaxf(rmax, red[i]);
    __syncthreads();

    v0.x = __expf(v0.x - rmax); v0.y = __expf(v0.y - rmax);
    v0.z = __expf(v0.z - rmax); v0.w = __expf(v0.w - rmax);
    v1.x = __expf(v1.x - rmax); v1.y = __expf(v1.y - rmax);
    v1.z = __expf(v1.z - rmax); v1.w = __expf(v1.w - rmax);
    float s = v0.x + v0.y + v0.z + v0.w + v1.x + v1.y + v1.z + v1.w;
#pragma unroll
    for (int o = 16; o; o >>= 1) s += __shfl_xor_sync(0xffffffffu, s, o);
    if (lane == 0) red[warp] = s;
    __syncthreads();
    float tot = 0.0f;
#pragma unroll
    for (int i = 0; i < 8; i++) tot += red[i];
    const float inv = 1.0f / tot;

    v0.x *= inv; v0.y *= inv; v0.z *= inv; v0.w *= inv;
    v1.x *= inv; v1.y *= inv; v1.z *= inv; v1.w *= inv;
    *reinterpret_cast<float4*>(&p[tid * 4])        = v0;
    *reinterpret_cast<float4*>(&p[tid * 4 + 1024]) = v1;

    __half* ph = wph + (long)blockIdx.x * SEQ;
#pragma unroll
    for (int half = 0; half < 2; half++) {
        float4 v = half ? v1 : v0;
        const int off = tid * 4 + half * 1024;
        __half2 a = __halves2half2(__float2half_rn(v.x), __float2half_rn(v.y));
        __half2 b = __halves2half2(__float2half_rn(v.z), __float2half_rn(v.w));
        uint2 u = make_uint2(*reinterpret_cast<uint32_t*>(&a),
                             *reinterpret_cast<uint32_t*>(&b));
        *reinterpret_cast<uint2*>(ph + off) = u;
    }
}

// ---------------------------------------------------------------------------
extern "C" void kernel_launch(void* const* d_in, const int* in_sizes, int n_in,
                              void* d_out, int out_size)
{
    const float* x  = (const float*)d_in[0];
    const float* Wq = (const float*)d_in[1];
    const float* bq = (const float*)d_in[2];

    float* out_attn = (float*)d_out;
    float* out_w    = out_attn + (long)ROWS * DIM;

    __half *xh, *xl, *wh, *wl, *qkh, *qkl, *vth, *vtl, *wph;
    cudaGetSymbolAddress((void**)&xh, g_xh);
    cudaGetSymbolAddress((void**)&xl, g_xl);
    cudaGetSymbolAddress((void**)&wh, g_wh);
    cudaGetSymbolAddress((void**)&wl, g_wl);
    cudaGetSymbolAddress((void**)&qkh, g_qkh);
    cudaGetSymbolAddress((void**)&qkl, g_qkl);
    cudaGetSymbolAddress((void**)&vth, g_vth);
    cudaGetSymbolAddress((void**)&vtl, g_vtl);
    cudaGetSymbolAddress((void**)&wph, g_wph);

    const int SM1 = 3 * (2 * 8192 + 16384);   // 3 stages x 32KB = 98304
    const int SM2 = 4 * (8192 + 16384);       // 4 stages x 24KB = 98304
    cudaFuncSetAttribute(mma_gemm<3, 1, 3>,
                         cudaFuncAttributeMaxDynamicSharedMemorySize, SM1);
    cudaFuncSetAttribute(mma_gemm<2, 0, 4>,
                         cudaFuncAttributeMaxDynamicSharedMemorySize, SM2);

    // 0) prepass: split x and W into fp16 planes
    split_planes<<<592, 256>>>(x, xh, xl, (long)ROWS * DIM / 4);
    split_planes<<<296, 256>>>(Wq, wh, wl, (long)3 * DIM * DIM / 4);

    // 1) qkv = x @ W^T + b (3-term) -> qk hi/lo planes + v^T hi/lo planes
    mma_gemm<3, 1, 3><<<dim3(24, 64, 1), 256, SM1>>>(
        xh, xl, wh, wl, bq, nullptr,
        qkh, qkl, vth, vtl,
        1024, 1024, 1024, 0, 0, 0, 0, 1.0f);

    // 2) scores = Qh @ (Kh+Kl)^T / 32 (2-term) -> fp32 w region
    mma_gemm<2, 0, 4><<<dim3(16, 16, BATCH), 256, SM2>>>(
        qkh, nullptr, qkh + 1024, qkl + 1024, nullptr, out_w,
        nullptr, nullptr, nullptr, nullptr,
        1024, 2048, 2048, 2048,
        (long)SEQ * 2048, (long)SEQ * 2048, (long)SEQ * SEQ, 1.0f / 32.0f);

    // 3) softmax rows in place + emit w hi plane
    softmax_rows_kernel<<<ROWS, 256>>>(out_w, wph);

    // 4) out = wh @ (Vh+Vl) (2-term) : M=2048, N=1024, K=2048, batched
    mma_gemm<2, 0, 4><<<dim3(8, 16, BATCH), 256, SM2>>>(
        wph, nullptr, vth, vtl, nullptr, out_attn,
        nullptr, nullptr, nullptr, nullptr,
        2048, 2048, 2048, 1024,
        (long)SEQ * SEQ, (long)DIM * SEQ, (long)SEQ * DIM, 1.0f);
}

// round 8
// speedup vs baseline: 4.6434x; 1.1691x over previous
#include <cuda_runtime.h>
#include <cuda_fp16.h>
#include <cstdint>

// ---------------------------------------------------------------------------
// MaskedAttention via fp16 asymmetric-split mma.sync GEMMs.
// All GEMMs 2-term: C = Ah·(Bh+Bl)  (A hi-only, B hi+lo), NT layout.
// GEMM1: qkv = xh·(Wh+Wl)+b -> Q/K hi+lo planes + V^T hi+lo planes.
// GEMM2: scores = Qh·(Kh+Kl)/32 -> fp32 w. softmax -> w fp32 + w hi plane.
// GEMM4: out = wh·(Vh+Vl).
// ---------------------------------------------------------------------------

#define BATCH 4
#define SEQ   2048
#define DIM   1024
#define ROWS  (BATCH * SEQ)      // 8192

__device__ __half g_xh[(long)ROWS * DIM];
__device__ __half g_wh[(long)3 * DIM * DIM];
__device__ __half g_wl[(long)3 * DIM * DIM];
__device__ __half g_qkh[(long)ROWS * 2048];
__device__ __half g_qkl[(long)ROWS * 2048];
__device__ __half g_vth[(long)BATCH * DIM * SEQ];
__device__ __half g_vtl[(long)BATCH * DIM * SEQ];
__device__ __half g_wph[(long)ROWS * SEQ];

__device__ __forceinline__ uint32_t smem_u32(const void* p) {
    uint32_t a;
    asm("{ .reg .u64 t; cvta.to.shared.u64 t, %1; cvt.u32.u64 %0, t; }"
        : "=r"(a) : "l"(p));
    return a;
}
__device__ __forceinline__ void cp_async16(uint32_t s, const void* g) {
    asm volatile("cp.async.cg.shared.global [%0], [%1], 16;" :: "r"(s), "l"(g));
}
__device__ __forceinline__ void cp_commit() {
    asm volatile("cp.async.commit_group;" ::: "memory");
}
template <int N>
__device__ __forceinline__ void cp_wait() {
    asm volatile("cp.async.wait_group %0;" :: "n"(N) : "memory");
}
__device__ __forceinline__ void ldsm4(uint32_t* r, uint32_t addr) {
    asm volatile("ldmatrix.sync.aligned.m8n8.x4.shared.b16 {%0,%1,%2,%3}, [%4];"
                 : "=r"(r[0]), "=r"(r[1]), "=r"(r[2]), "=r"(r[3]) : "r"(addr));
}
__device__ __forceinline__ void hmma(float* c, const uint32_t* a, uint32_t b0, uint32_t b1) {
    asm volatile(
        "mma.sync.aligned.m16n8k16.row.col.f32.f16.f16.f32 "
        "{%0,%1,%2,%3}, {%4,%5,%6,%7}, {%8,%9}, {%0,%1,%2,%3};"
        : "+f"(c[0]), "+f"(c[1]), "+f"(c[2]), "+f"(c[3])
        : "r"(a[0]), "r"(a[1]), "r"(a[2]), "r"(a[3]), "r"(b0), "r"(b1));
}
__device__ __forceinline__ void split_h(float v, __half& h, __half& l) {
    h = __float2half_rn(v);
    l = __float2half_rn(v - __half2float(h));
}

// ---------------------------------------------------------------------------
// LO=1: emit hi+lo planes; LO=0: hi only.
template <int LO>
__global__ __launch_bounds__(256) void split_planes(
    const float* __restrict__ src,
    __half* __restrict__ hi, __half* __restrict__ lo, long n4)
{
    for (long i = blockIdx.x * 256 + threadIdx.x; i < n4; i += (long)gridDim.x * 256) {
        float4 v = *reinterpret_cast<const float4*>(src + i * 4);
        __half h0, h1, h2, h3, l0, l1, l2, l3;
        split_h(v.x, h0, l0); split_h(v.y, h1, l1);
        split_h(v.z, h2, l2); split_h(v.w, h3, l3);
        __half2 a = __halves2half2(h0, h1), b = __halves2half2(h2, h3);
        uint2 uh = make_uint2(*reinterpret_cast<uint32_t*>(&a),
                              *reinterpret_cast<uint32_t*>(&b));
        *reinterpret_cast<uint2*>(hi + i * 4) = uh;
        if (LO) {
            __half2 c = __halves2half2(l0, l1), d = __halves2half2(l2, l3);
            uint2 ul = make_uint2(*reinterpret_cast<uint32_t*>(&c),
                                  *reinterpret_cast<uint32_t*>(&d));
            *reinterpret_cast<uint2*>(lo + i * 4) = ul;
        }
    }
}

// ---------------------------------------------------------------------------
// 2-term GEMM: C = scale * Ah·(Bh+Bl)^T (+ bias).
// EPI: 0 = fp32 C, 1 = GEMM1 epilogue (bias, fp16 planes out).
// A tile: 64 phys rows x 128B = 8KB. B tile: 128 rows x 128B hi|lo = 16KB.
// 4 stages x 24KB = 96KB smem, 2 CTAs/SM.
// ---------------------------------------------------------------------------
#define STG 4
#define BUFS 24576
#define OFFB 8192

template <int EPI>
__global__ __launch_bounds__(256, 2) void mma_gemm(
    const __half* __restrict__ Ah,
    const __half* __restrict__ Bh, const __half* __restrict__ Bl,
    const float* __restrict__ bias, float* __restrict__ C,
    __half* __restrict__ qkh, __half* __restrict__ qkl,
    __half* __restrict__ vth, __half* __restrict__ vtl,
    int K, int lda, int ldb, int ldc,
    long sA, long sB, long sC, float scale)
{
    extern __shared__ char ds[];
    const int tid  = threadIdx.x;
    const int wid  = tid >> 5;
    const int lane = tid & 31;
    const int bm   = blockIdx.y * 128;
    const int bn   = blockIdx.x * 128;
    const int z    = blockIdx.z;

    Ah += z * sA + (long)bm * lda;
    Bh += z * sB + (long)bn * ldb;
    Bl += z * sB + (long)bn * ldb;

    const int wm = (wid >> 2) << 6;     // 0 or 64
    const int wn = (wid & 3) << 5;      // 0,32,64,96

    float acc[4][4][4];
#pragma unroll
    for (int a = 0; a < 4; a++)
#pragma unroll
        for (int b = 0; b < 4; b++)
#pragma unroll
            for (int c = 0; c < 4; c++) acc[a][b][c] = 0.0f;

    const int nck = K >> 5;
    const uint32_t sb0 = smem_u32(ds);

    auto issue = [&](int ck) {
        const int k0 = ck << 5;
        const uint32_t sbase = sb0 + (ck % STG) * BUFS;
#pragma unroll
        for (int t = 0; t < 2; t++) {
            const int i = tid + t * 256;          // 0..511
            const int r = i >> 2, c = i & 3;
            const __half* src = Ah + (long)r * lda + k0 + c * 8;
            const int pr = r & 63, cc = ((r >> 6) << 2) | c;
            cp_async16(sbase + pr * 128 + ((cc ^ (pr & 7)) << 4), src);
        }
#pragma unroll
        for (int t = 0; t < 4; t++) {
            const int i = tid + t * 256;          // 0..1023
            const int pl = i >> 9, j2 = i & 511, r = j2 >> 2, c = j2 & 3;
            const __half* src = (pl ? Bl : Bh) + (long)r * ldb + k0 + c * 8;
            cp_async16(sbase + OFFB + r * 128 + (((c + (pl ? 4 : 0)) ^ (r & 7)) << 4), src);
        }
        cp_commit();
    };

#pragma unroll
    for (int i = 0; i < STG - 1; i++) issue(i);

    // ldsm per-lane constants
    const int j = lane >> 3;
    const int arow = ((j & 1) << 3) | (lane & 7);
    const int acnk = j >> 1;
    const int brow = ((j >> 1) << 3) | (lane & 7);
    const int bcnk = j & 1;
    const int r7a = arow & 7;
    const int r7b = brow & 7;
    const int hiBit4 = (wm >> 6) << 2;   // A col-block select (0 or 4)

    for (int ck = 0; ck < nck; ck++) {
        cp_wait<STG - 2>();
        __syncthreads();
        if (ck + STG - 1 < nck) issue(ck + STG - 1);

        const uint32_t bfA = sb0 + (ck % STG) * BUFS;
        const uint32_t bfB = bfA + OFFB;
#pragma unroll
        for (int s = 0; s < 2; s++) {
            const int c0 = s * 2;
            uint32_t ah[4][4], bh[2][4], bl[2][4];
#pragma unroll
            for (int mt = 0; mt < 4; mt++) {
                const int pr = (mt << 4) + arow;      // 0..63
                const int cc = hiBit4 + c0 + acnk;
                ldsm4(ah[mt], bfA + pr * 128 + ((cc ^ r7a) << 4));
            }
#pragma unroll
            for (int nt2 = 0; nt2 < 2; nt2++) {
                const int r = wn + (nt2 << 4) + brow;
                const uint32_t rb = bfB + r * 128;
                ldsm4(bh[nt2], rb + (((c0 + bcnk) ^ r7b) << 4));
                ldsm4(bl[nt2], rb + (((c0 + bcnk + 4) ^ r7b) << 4));
            }
#pragma unroll
            for (int mt = 0; mt < 4; mt++)
#pragma unroll
                for (int nt = 0; nt < 4; nt++) {
                    const int g = nt >> 1, q = (nt & 1) << 1;
                    hmma(acc[mt][nt], ah[mt], bh[g][q], bh[g][q + 1]);
                    hmma(acc[mt][nt], ah[mt], bl[g][q], bl[g][q + 1]);
                }
        }
    }

    // ---- epilogue
    const int mrow = lane >> 2;
    const int ncol = (lane & 3) << 1;
    if (EPI == 0) {
        float* Cz = C + (long)z * sC;
#pragma unroll
        for (int mt = 0; mt < 4; mt++) {
            const int m = bm + wm + (mt << 4) + mrow;
#pragma unroll
            for (int nt = 0; nt < 4; nt++) {
                const int n = bn + wn + (nt << 3) + ncol;
                float2 v0 = make_float2(acc[mt][nt][0] * scale, acc[mt][nt][1] * scale);
                float2 v1 = make_float2(acc[mt][nt][2] * scale, acc[mt][nt][3] * scale);
                *reinterpret_cast<float2*>(Cz + (long)m * ldc + n) = v0;
                *reinterpret_cast<float2*>(Cz + (long)(m + 8) * ldc + n) = v1;
            }
        }
    } else {
#pragma unroll
        for (int mt = 0; mt < 4; mt++) {
            const int m0 = bm + wm + (mt << 4) + mrow;
            const int m1 = m0 + 8;
#pragma unroll
            for (int nt = 0; nt < 4; nt++) {
                const int n = bn + wn + (nt << 3) + ncol;
                const float b0 = bias[n], b1 = bias[n + 1];
                float v00 = acc[mt][nt][0] + b0, v01 = acc[mt][nt][1] + b1;
                float v10 = acc[mt][nt][2] + b0, v11 = acc[mt][nt][3] + b1;
                __half h00, h01, h10, h11, l00, l01, l10, l11;
                split_h(v00, h00, l00); split_h(v01, h01, l01);
                split_h(v10, h10, l10); split_h(v11, h11, l11);
                if (n < 2048) {
                    __half2 ph0 = __halves2half2(h00, h01);
                    __half2 pl0 = __halves2half2(l00, l01);
                    __half2 ph1 = __halves2half2(h10, h11);
                    __half2 pl1 = __halves2half2(l10, l11);
                    *reinterpret_cast<__half2*>(&qkh[(long)m0 * 2048 + n]) = ph0;
                    *reinterpret_cast<__half2*>(&qkl[(long)m0 * 2048 + n]) = pl0;
                    *reinterpret_cast<__half2*>(&qkh[(long)m1 * 2048 + n]) = ph1;
                    *reinterpret_cast<__half2*>(&qkl[(long)m1 * 2048 + n]) = pl1;
                } else {
                    const int d = n - 2048;
                    const int bi0 = m0 >> 11, s0 = m0 & 2047;
                    const int bi1 = m1 >> 11, s1 = m1 & 2047;
                    __half* th0 = vth + (long)bi0 * DIM * SEQ + (long)d * SEQ + s0;
                    __half* tl0 = vtl + (long)bi0 * DIM * SEQ + (long)d * SEQ + s0;
                    __half* th1 = vth + (long)bi1 * DIM * SEQ + (long)d * SEQ + s1;
                    __half* tl1 = vtl + (long)bi1 * DIM * SEQ + (long)d * SEQ + s1;
                    th0[0] = h00; th0[SEQ] = h01; tl0[0] = l00; tl0[SEQ] = l01;
                    th1[0] = h10; th1[SEQ] = h11; tl1[0] = l10; tl1[SEQ] = l11;
                }
            }
        }
    }
}

// ---------------------------------------------------------------------------
__global__ __launch_bounds__(256) void softmax_rows_kernel(
    float* __restrict__ w, __half* __restrict__ wph)
{
    float* p = w + (long)blockIdx.x * SEQ;
    const int tid  = threadIdx.x;
    const int lane = tid & 31;
    const int warp = tid >> 5;

    float4 v0 = *reinterpret_cast<const float4*>(&p[tid * 4]);
    float4 v1 = *reinterpret_cast<const float4*>(&p[tid * 4 + 1024]);

    float m = fmaxf(fmaxf(fmaxf(v0.x, v0.y), fmaxf(v0.z, v0.w)),
                    fmaxf(fmaxf(v1.x, v1.y), fmaxf(v1.z, v1.w)));
    __shared__ float red[8];
#pragma unroll
    for (int o = 16; o; o >>= 1) m = fmaxf(m, __shfl_xor_sync(0xffffffffu, m, o));
    if (lane == 0) red[warp] = m;
    __syncthreads();
    float rmax = red[0];
#pragma unroll
    for (int i = 1; i < 8; i++) rmax = fmaxf(rmax, red[i]);
    __syncthreads();

    v0.x = __expf(v0.x - rmax); v0.y = __expf(v0.y - rmax);
    v0.z = __expf(v0.z - rmax); v0.w = __expf(v0.w - rmax);
    v1.x = __expf(v1.x - rmax); v1.y = __expf(v1.y - rmax);
    v1.z = __expf(v1.z - rmax); v1.w = __expf(v1.w - rmax);
    float s = v0.x + v0.y + v0.z + v0.w + v1.x + v1.y + v1.z + v1.w;
#pragma unroll
    for (int o = 16; o; o >>= 1) s += __shfl_xor_sync(0xffffffffu, s, o);
    if (lane == 0) red[warp] = s;
    __syncthreads();
    float tot = 0.0f;
#pragma unroll
    for (int i = 0; i < 8; i++) tot += red[i];
    const float inv = 1.0f / tot;

    v0.x *= inv; v0.y *= inv; v0.z *= inv; v0.w *= inv;
    v1.x *= inv; v1.y *= inv; v1.z *= inv; v1.w *= inv;
    *reinterpret_cast<float4*>(&p[tid * 4])        = v0;
    *reinterpret_cast<float4*>(&p[tid * 4 + 1024]) = v1;

    __half* ph = wph + (long)blockIdx.x * SEQ;
#pragma unroll
    for (int half = 0; half < 2; half++) {
        float4 v = half ? v1 : v0;
        const int off = tid * 4 + half * 1024;
        __half2 a = __halves2half2(__float2half_rn(v.x), __float2half_rn(v.y));
        __half2 b = __halves2half2(__float2half_rn(v.z), __float2half_rn(v.w));
        uint2 u = make_uint2(*reinterpret_cast<uint32_t*>(&a),
                             *reinterpret_cast<uint32_t*>(&b));
        *reinterpret_cast<uint2*>(ph + off) = u;
    }
}

// ---------------------------------------------------------------------------
extern "C" void kernel_launch(void* const* d_in, const int* in_sizes, int n_in,
                              void* d_out, int out_size)
{
    const float* x  = (const float*)d_in[0];
    const float* Wq = (const float*)d_in[1];
    const float* bq = (const float*)d_in[2];

    float* out_attn = (float*)d_out;
    float* out_w    = out_attn + (long)ROWS * DIM;

    __half *xh, *wh, *wl, *qkh, *qkl, *vth, *vtl, *wph;
    cudaGetSymbolAddress((void**)&xh, g_xh);
    cudaGetSymbolAddress((void**)&wh, g_wh);
    cudaGetSymbolAddress((void**)&wl, g_wl);
    cudaGetSymbolAddress((void**)&qkh, g_qkh);
    cudaGetSymbolAddress((void**)&qkl, g_qkl);
    cudaGetSymbolAddress((void**)&vth, g_vth);
    cudaGetSymbolAddress((void**)&vtl, g_vtl);
    cudaGetSymbolAddress((void**)&wph, g_wph);

    const int SMEM = STG * BUFS;          // 98304
    cudaFuncSetAttribute(mma_gemm<0>,
                         cudaFuncAttributeMaxDynamicSharedMemorySize, SMEM);
    cudaFuncSetAttribute(mma_gemm<1>,
                         cudaFuncAttributeMaxDynamicSharedMemorySize, SMEM);

    // 0) prepass: x -> hi plane only; W -> hi+lo planes
    split_planes<0><<<592, 256>>>(x, xh, nullptr, (long)ROWS * DIM / 4);
    split_planes<1><<<296, 256>>>(Wq, wh, wl, (long)3 * DIM * DIM / 4);

    // 1) qkv = xh @ (Wh+Wl)^T + b -> qk hi/lo planes + v^T hi/lo planes
    mma_gemm<1><<<dim3(24, 64, 1), 256, SMEM>>>(
        xh, wh, wl, bq, nullptr,
        qkh, qkl, vth, vtl,
        1024, 1024, 1024, 0, 0, 0, 0, 1.0f);

    // 2) scores = Qh @ (Kh+Kl)^T / 32 -> fp32 w region
    mma_gemm<0><<<dim3(16, 16, BATCH), 256, SMEM>>>(
        qkh, qkh + 1024, qkl + 1024, nullptr, out_w,
        nullptr, nullptr, nullptr, nullptr,
        1024, 2048, 2048, 2048,
        (long)SEQ * 2048, (long)SEQ * 2048, (long)SEQ * SEQ, 1.0f / 32.0f);

    // 3) softmax rows in place + emit w hi plane
    softmax_rows_kernel<<<ROWS, 256>>>(out_w, wph);

    // 4) out = wh @ (Vh+Vl)^T : M=2048, N=1024, K=2048, batched
    mma_gemm<0><<<dim3(8, 16, BATCH), 256, SMEM>>>(
        wph, vth, vtl, nullptr, out_attn,
        nullptr, nullptr, nullptr, nullptr,
        2048, 2048, 2048, 1024,
        (long)SEQ * SEQ, (long)DIM * SEQ, (long)SEQ * DIM, 1.0f);
}

// round 9
// speedup vs baseline: 5.9314x; 1.2774x over previous
#include <cuda_runtime.h>
#include <cuda_fp16.h>
#include <cstdint>

// ---------------------------------------------------------------------------
// MaskedAttention via fp16 mma.sync GEMMs.
// GEMM1 (2-term): qkv = xh·(Wh+Wl)+b -> Qh/Kh planes + Vh^T plane.
// GEMM2 (1-term): scores = Qh·Kh/32 -> fp32 w. softmax -> w fp32 + wh plane.
// GEMM4 (1-term): out = wh·Vh.   All NT: C[m,n]=scale*sum_k A[m,k]B[n,k].
// ---------------------------------------------------------------------------

#define BATCH 4
#define SEQ   2048
#define DIM   1024
#define ROWS  (BATCH * SEQ)      // 8192

__device__ __half g_xh[(long)ROWS * DIM];
__device__ __half g_wh[(long)3 * DIM * DIM];
__device__ __half g_wl[(long)3 * DIM * DIM];
__device__ __half g_qkh[(long)ROWS * 2048];           // Q|K hi plane
__device__ __half g_vth[(long)BATCH * DIM * SEQ];     // V^T hi plane
__device__ __half g_wph[(long)ROWS * SEQ];            // softmax(w) hi plane

__device__ __forceinline__ uint32_t smem_u32(const void* p) {
    uint32_t a;
    asm("{ .reg .u64 t; cvta.to.shared.u64 t, %1; cvt.u32.u64 %0, t; }"
        : "=r"(a) : "l"(p));
    return a;
}
__device__ __forceinline__ void cp_async16(uint32_t s, const void* g) {
    asm volatile("cp.async.cg.shared.global [%0], [%1], 16;" :: "r"(s), "l"(g));
}
__device__ __forceinline__ void cp_commit() {
    asm volatile("cp.async.commit_group;" ::: "memory");
}
template <int N>
__device__ __forceinline__ void cp_wait() {
    asm volatile("cp.async.wait_group %0;" :: "n"(N) : "memory");
}
__device__ __forceinline__ void ldsm4(uint32_t* r, uint32_t addr) {
    asm volatile("ldmatrix.sync.aligned.m8n8.x4.shared.b16 {%0,%1,%2,%3}, [%4];"
                 : "=r"(r[0]), "=r"(r[1]), "=r"(r[2]), "=r"(r[3]) : "r"(addr));
}
__device__ __forceinline__ void hmma(float* c, const uint32_t* a, uint32_t b0, uint32_t b1) {
    asm volatile(
        "mma.sync.aligned.m16n8k16.row.col.f32.f16.f16.f32 "
        "{%0,%1,%2,%3}, {%4,%5,%6,%7}, {%8,%9}, {%0,%1,%2,%3};"
        : "+f"(c[0]), "+f"(c[1]), "+f"(c[2]), "+f"(c[3])
        : "r"(a[0]), "r"(a[1]), "r"(a[2]), "r"(a[3]), "r"(b0), "r"(b1));
}
__device__ __forceinline__ void split_h(float v, __half& h, __half& l) {
    h = __float2half_rn(v);
    l = __float2half_rn(v - __half2float(h));
}

// ---------------------------------------------------------------------------
// LO=1: emit hi+lo planes; LO=0: hi only.
template <int LO>
__global__ __launch_bounds__(256) void split_planes(
    const float* __restrict__ src,
    __half* __restrict__ hi, __half* __restrict__ lo, long n4)
{
    for (long i = blockIdx.x * 256 + threadIdx.x; i < n4; i += (long)gridDim.x * 256) {
        float4 v = *reinterpret_cast<const float4*>(src + i * 4);
        __half h0, h1, h2, h3, l0, l1, l2, l3;
        split_h(v.x, h0, l0); split_h(v.y, h1, l1);
        split_h(v.z, h2, l2); split_h(v.w, h3, l3);
        __half2 a = __halves2half2(h0, h1), b = __halves2half2(h2, h3);
        uint2 uh = make_uint2(*reinterpret_cast<uint32_t*>(&a),
                              *reinterpret_cast<uint32_t*>(&b));
        *reinterpret_cast<uint2*>(hi + i * 4) = uh;
        if (LO) {
            __half2 c = __halves2half2(l0, l1), d = __halves2half2(l2, l3);
            uint2 ul = make_uint2(*reinterpret_cast<uint32_t*>(&c),
                                  *reinterpret_cast<uint32_t*>(&d));
            *reinterpret_cast<uint2*>(lo + i * 4) = ul;
        }
    }
}

// ---------------------------------------------------------------------------
// GEMM: C = scale * Ah·Bsum^T (+ bias). BPL = B planes (1 or 2).
// EPI: 0 = fp32 C, 1 = GEMM1 epilogue (bias, hi planes out).
// A tile: 128 rows packed as 64 phys x 128B = 8KB. B: same if BPL=1, else
// 128 rows x 128B (hi chunks 0-3 | lo 4-7) = 16KB.
// ---------------------------------------------------------------------------
template <int BPL, int EPI, int STG>
__global__ __launch_bounds__(256, 2) void mma_gemm(
    const __half* __restrict__ Ah,
    const __half* __restrict__ Bh, const __half* __restrict__ Bl,
    const float* __restrict__ bias, float* __restrict__ C,
    __half* __restrict__ qkh, __half* __restrict__ vth,
    int K, int lda, int ldb, int ldc,
    long sA, long sB, long sC, float scale)
{
    constexpr int OFFB = 8192;
    constexpr int BUFS = OFFB + BPL * 8192;

    extern __shared__ char ds[];
    const int tid  = threadIdx.x;
    const int wid  = tid >> 5;
    const int lane = tid & 31;
    const int bm   = blockIdx.y * 128;
    const int bn   = blockIdx.x * 128;
    const int z    = blockIdx.z;

    Ah += z * sA + (long)bm * lda;
    Bh += z * sB + (long)bn * ldb;
    if (BPL == 2) Bl += z * sB + (long)bn * ldb;

    const int wm = (wid >> 2) << 6;     // 0 or 64
    const int wn = (wid & 3) << 5;      // 0,32,64,96

    float acc[4][4][4];
#pragma unroll
    for (int a = 0; a < 4; a++)
#pragma unroll
        for (int b = 0; b < 4; b++)
#pragma unroll
            for (int c = 0; c < 4; c++) acc[a][b][c] = 0.0f;

    const int nck = K >> 5;
    const uint32_t sb0 = smem_u32(ds);

    auto issue = [&](int ck) {
        const int k0 = ck << 5;
        const uint32_t sbase = sb0 + (ck % STG) * BUFS;
#pragma unroll
        for (int t = 0; t < 2; t++) {
            const int i = tid + t * 256;          // 0..511
            const int r = i >> 2, c = i & 3;
            const __half* src = Ah + (long)r * lda + k0 + c * 8;
            const int pr = r & 63, cc = ((r >> 6) << 2) | c;
            cp_async16(sbase + pr * 128 + ((cc ^ (pr & 7)) << 4), src);
        }
        if (BPL == 1) {
#pragma unroll
            for (int t = 0; t < 2; t++) {
                const int i = tid + t * 256;      // 0..511
                const int r = i >> 2, c = i & 3;
                const __half* src = Bh + (long)r * ldb + k0 + c * 8;
                const int pr = r & 63, cc = ((r >> 6) << 2) | c;
                cp_async16(sbase + OFFB + pr * 128 + ((cc ^ (pr & 7)) << 4), src);
            }
        } else {
#pragma unroll
            for (int t = 0; t < 4; t++) {
                const int i = tid + t * 256;      // 0..1023
                const int pl = i >> 9, j2 = i & 511, r = j2 >> 2, c = j2 & 3;
                const __half* src = (pl ? Bl : Bh) + (long)r * ldb + k0 + c * 8;
                cp_async16(sbase + OFFB + r * 128 +
                           (((c + (pl ? 4 : 0)) ^ (r & 7)) << 4), src);
            }
        }
        cp_commit();
    };

#pragma unroll
    for (int i = 0; i < STG - 1; i++) issue(i);

    // ldsm per-lane constants
    const int j = lane >> 3;
    const int arow = ((j & 1) << 3) | (lane & 7);
    const int acnk = j >> 1;
    const int brow = ((j >> 1) << 3) | (lane & 7);
    const int bcnk = j & 1;
    const int r7a = arow & 7;
    const int r7b = brow & 7;
    const int hiA4 = (wm >> 6) << 2;     // A col-block select (0 or 4)

    for (int ck = 0; ck < nck; ck++) {
        cp_wait<STG - 2>();
        __syncthreads();
        if (ck + STG - 1 < nck) issue(ck + STG - 1);

        const uint32_t bfA = sb0 + (ck % STG) * BUFS;
        const uint32_t bfB = bfA + OFFB;
#pragma unroll
        for (int s = 0; s < 2; s++) {
            const int c0 = s * 2;
            uint32_t ah[4][4], bh[2][4], bl[2][4];
#pragma unroll
            for (int mt = 0; mt < 4; mt++) {
                const int pr = (mt << 4) + arow;      // 0..63
                const int cc = hiA4 + c0 + acnk;
                ldsm4(ah[mt], bfA + pr * 128 + ((cc ^ r7a) << 4));
            }
#pragma unroll
            for (int nt2 = 0; nt2 < 2; nt2++) {
                const int r = wn + (nt2 << 4) + brow;
                if (BPL == 1) {
                    const int pr = r & 63;
                    const int cc = ((r >> 6) << 2) + c0 + bcnk;
                    ldsm4(bh[nt2], bfB + pr * 128 + ((cc ^ r7b) << 4));
                } else {
                    const uint32_t rb = bfB + r * 128;
                    ldsm4(bh[nt2], rb + (((c0 + bcnk) ^ r7b) << 4));
                    ldsm4(bl[nt2], rb + (((c0 + bcnk + 4) ^ r7b) << 4));
                }
            }
#pragma unroll
            for (int mt = 0; mt < 4; mt++)
#pragma unroll
                for (int nt = 0; nt < 4; nt++) {
                    const int g = nt >> 1, q = (nt & 1) << 1;
                    hmma(acc[mt][nt], ah[mt], bh[g][q], bh[g][q + 1]);
                    if (BPL == 2)
                        hmma(acc[mt][nt], ah[mt], bl[g][q], bl[g][q + 1]);
                }
        }
    }

    // ---- epilogue
    const int mrow = lane >> 2;
    const int ncol = (lane & 3) << 1;
    if (EPI == 0) {
        float* Cz = C + (long)z * sC;
#pragma unroll
        for (int mt = 0; mt < 4; mt++) {
            const int m = bm + wm + (mt << 4) + mrow;
#pragma unroll
            for (int nt = 0; nt < 4; nt++) {
                const int n = bn + wn + (nt << 3) + ncol;
                float2 v0 = make_float2(acc[mt][nt][0] * scale, acc[mt][nt][1] * scale);
                float2 v1 = make_float2(acc[mt][nt][2] * scale, acc[mt][nt][3] * scale);
                *reinterpret_cast<float2*>(Cz + (long)m * ldc + n) = v0;
                *reinterpret_cast<float2*>(Cz + (long)(m + 8) * ldc + n) = v1;
            }
        }
    } else {
#pragma unroll
        for (int mt = 0; mt < 4; mt++) {
            const int m0 = bm + wm + (mt << 4) + mrow;
            const int m1 = m0 + 8;
#pragma unroll
            for (int nt = 0; nt < 4; nt++) {
                const int n = bn + wn + (nt << 3) + ncol;
                const float b0 = bias[n], b1 = bias[n + 1];
                __half h00 = __float2half_rn(acc[mt][nt][0] + b0);
                __half h01 = __float2half_rn(acc[mt][nt][1] + b1);
                __half h10 = __float2half_rn(acc[mt][nt][2] + b0);
                __half h11 = __float2half_rn(acc[mt][nt][3] + b1);
                if (n < 2048) {
                    *reinterpret_cast<__half2*>(&qkh[(long)m0 * 2048 + n]) =
                        __halves2half2(h00, h01);
                    *reinterpret_cast<__half2*>(&qkh[(long)m1 * 2048 + n]) =
                        __halves2half2(h10, h11);
                } else {
                    const int d = n - 2048;
                    const int bi0 = m0 >> 11, s0 = m0 & 2047;
                    const int bi1 = m1 >> 11, s1 = m1 & 2047;
                    __half* t0 = vth + (long)bi0 * DIM * SEQ + (long)d * SEQ + s0;
                    __half* t1 = vth + (long)bi1 * DIM * SEQ + (long)d * SEQ + s1;
                    t0[0] = h00; t0[SEQ] = h01;
                    t1[0] = h10; t1[SEQ] = h11;
                }
            }
        }
    }
}

// ---------------------------------------------------------------------------
__global__ __launch_bounds__(256) void softmax_rows_kernel(
    float* __restrict__ w, __half* __restrict__ wph)
{
    float* p = w + (long)blockIdx.x * SEQ;
    const int tid  = threadIdx.x;
    const int lane = tid & 31;
    const int warp = tid >> 5;

    float4 v0 = *reinterpret_cast<const float4*>(&p[tid * 4]);
    float4 v1 = *reinterpret_cast<const float4*>(&p[tid * 4 + 1024]);

    float m = fmaxf(fmaxf(fmaxf(v0.x, v0.y), fmaxf(v0.z, v0.w)),
                    fmaxf(fmaxf(v1.x, v1.y), fmaxf(v1.z, v1.w)));
    __shared__ float red[8];
#pragma unroll
    for (int o = 16; o; o >>= 1) m = fmaxf(m, __shfl_xor_sync(0xffffffffu, m, o));
    if (lane == 0) red[warp] = m;
    __syncthreads();
    float rmax = red[0];
#pragma unroll
    for (int i = 1; i < 8; i++) rmax = fmaxf(rmax, red[i]);
    __syncthreads();

    v0.x = __expf(v0.x - rmax); v0.y = __expf(v0.y - rmax);
    v0.z = __expf(v0.z - rmax); v0.w = __expf(v0.w - rmax);
    v1.x = __expf(v1.x - rmax); v1.y = __expf(v1.y - rmax);
    v1.z = __expf(v1.z - rmax); v1.w = __expf(v1.w - rmax);
    float s = v0.x + v0.y + v0.z + v0.w + v1.x + v1.y + v1.z + v1.w;
#pragma unroll
    for (int o = 16; o; o >>= 1) s += __shfl_xor_sync(0xffffffffu, s, o);
    if (lane == 0) red[warp] = s;
    __syncthreads();
    float tot = 0.0f;
#pragma unroll
    for (int i = 0; i < 8; i++) tot += red[i];
    const float inv = 1.0f / tot;

    v0.x *= inv; v0.y *= inv; v0.z *= inv; v0.w *= inv;
    v1.x *= inv; v1.y *= inv; v1.z *= inv; v1.w *= inv;
    *reinterpret_cast<float4*>(&p[tid * 4])        = v0;
    *reinterpret_cast<float4*>(&p[tid * 4 + 1024]) = v1;

    __half* ph = wph + (long)blockIdx.x * SEQ;
#pragma unroll
    for (int half = 0; half < 2; half++) {
        float4 v = half ? v1 : v0;
        const int off = tid * 4 + half * 1024;
        __half2 a = __halves2half2(__float2half_rn(v.x), __float2half_rn(v.y));
        __half2 b = __halves2half2(__float2half_rn(v.z), __float2half_rn(v.w));
        uint2 u = make_uint2(*reinterpret_cast<uint32_t*>(&a),
                             *reinterpret_cast<uint32_t*>(&b));
        *reinterpret_cast<uint2*>(ph + off) = u;
    }
}

// ---------------------------------------------------------------------------
extern "C" void kernel_launch(void* const* d_in, const int* in_sizes, int n_in,
                              void* d_out, int out_size)
{
    const float* x  = (const float*)d_in[0];
    const float* Wq = (const float*)d_in[1];
    const float* bq = (const float*)d_in[2];

    float* out_attn = (float*)d_out;
    float* out_w    = out_attn + (long)ROWS * DIM;

    __half *xh, *wh, *wl, *qkh, *vth, *wph;
    cudaGetSymbolAddress((void**)&xh, g_xh);
    cudaGetSymbolAddress((void**)&wh, g_wh);
    cudaGetSymbolAddress((void**)&wl, g_wl);
    cudaGetSymbolAddress((void**)&qkh, g_qkh);
    cudaGetSymbolAddress((void**)&vth, g_vth);
    cudaGetSymbolAddress((void**)&wph, g_wph);

    const int SM1 = 4 * 24576;   // GEMM1: BPL=2, 4 stages = 98304
    const int SM2 = 6 * 16384;   // GEMM2/4: BPL=1, 6 stages = 98304
    cudaFuncSetAttribute(mma_gemm<2, 1, 4>,
                         cudaFuncAttributeMaxDynamicSharedMemorySize, SM1);
    cudaFuncSetAttribute(mma_gemm<1, 0, 6>,
                         cudaFuncAttributeMaxDynamicSharedMemorySize, SM2);

    // 0) prepass: x -> hi plane; W -> hi+lo planes
    split_planes<0><<<592, 256>>>(x, xh, nullptr, (long)ROWS * DIM / 4);
    split_planes<1><<<296, 256>>>(Wq, wh, wl, (long)3 * DIM * DIM / 4);

    // 1) qkv = xh @ (Wh+Wl)^T + b -> Q|K hi plane + V^T hi plane
    mma_gemm<2, 1, 4><<<dim3(24, 64, 1), 256, SM1>>>(
        xh, wh, wl, bq, nullptr,
        qkh, vth,
        1024, 1024, 1024, 0, 0, 0, 0, 1.0f);

    // 2) scores = Qh @ Kh^T / 32 -> fp32 w region
    mma_gemm<1, 0, 6><<<dim3(16, 16, BATCH), 256, SM2>>>(
        qkh, qkh + 1024, nullptr, nullptr, out_w,
        nullptr, nullptr,
        1024, 2048, 2048, 2048,
        (long)SEQ * 2048, (long)SEQ * 2048, (long)SEQ * SEQ, 1.0f / 32.0f);

    // 3) softmax rows in place + emit w hi plane
    softmax_rows_kernel<<<ROWS, 256>>>(out_w, wph);

    // 4) out = wh @ Vh^T : M=2048, N=1024, K=2048, batched
    mma_gemm<1, 0, 6><<<dim3(8, 16, BATCH), 256, SM2>>>(
        wph, vth, nullptr, nullptr, out_attn,
        nullptr, nullptr,
        2048, 2048, 2048, 1024,
        (long)SEQ * SEQ, (long)DIM * SEQ, (long)SEQ * DIM, 1.0f);
}

// round 10
// speedup vs baseline: 7.4606x; 1.2578x over previous
#include <cuda_runtime.h>
#include <cuda_fp16.h>
#include <cstdint>

// ---------------------------------------------------------------------------
// MaskedAttention via single-plane fp16 mma.sync GEMMs.
// GEMM1: qkv = xh·Wh+b -> Qh/Kh planes + Vh^T plane.
// GEMM2: scores = Qh·Kh/32 -> fp32 w. softmax -> w fp32 + wh plane.
// GEMM4: out = wh·Vh.   All NT: C[m,n]=scale*sum_k A[m,k]B[n,k].
// ---------------------------------------------------------------------------

#define BATCH 4
#define SEQ   2048
#define DIM   1024
#define ROWS  (BATCH * SEQ)      // 8192

__device__ __half g_xh[(long)ROWS * DIM];
__device__ __half g_wh[(long)3 * DIM * DIM];
__device__ __half g_qkh[(long)ROWS * 2048];           // Q|K hi plane
__device__ __half g_vth[(long)BATCH * DIM * SEQ];     // V^T hi plane
__device__ __half g_wph[(long)ROWS * SEQ];            // softmax(w) hi plane

#define STG  6
#define BUFS 16384
#define OFFB 8192

__device__ __forceinline__ uint32_t smem_u32(const void* p) {
    uint32_t a;
    asm("{ .reg .u64 t; cvta.to.shared.u64 t, %1; cvt.u32.u64 %0, t; }"
        : "=r"(a) : "l"(p));
    return a;
}
__device__ __forceinline__ void cp_async16(uint32_t s, const void* g) {
    asm volatile("cp.async.cg.shared.global [%0], [%1], 16;" :: "r"(s), "l"(g));
}
__device__ __forceinline__ void cp_commit() {
    asm volatile("cp.async.commit_group;" ::: "memory");
}
template <int N>
__device__ __forceinline__ void cp_wait() {
    asm volatile("cp.async.wait_group %0;" :: "n"(N) : "memory");
}
__device__ __forceinline__ void ldsm4(uint32_t* r, uint32_t addr) {
    asm volatile("ldmatrix.sync.aligned.m8n8.x4.shared.b16 {%0,%1,%2,%3}, [%4];"
                 : "=r"(r[0]), "=r"(r[1]), "=r"(r[2]), "=r"(r[3]) : "r"(addr));
}
__device__ __forceinline__ void hmma(float* c, const uint32_t* a, uint32_t b0, uint32_t b1) {
    asm volatile(
        "mma.sync.aligned.m16n8k16.row.col.f32.f16.f16.f32 "
        "{%0,%1,%2,%3}, {%4,%5,%6,%7}, {%8,%9}, {%0,%1,%2,%3};"
        : "+f"(c[0]), "+f"(c[1]), "+f"(c[2]), "+f"(c[3])
        : "r"(a[0]), "r"(a[1]), "r"(a[2]), "r"(a[3]), "r"(b0), "r"(b1));
}

// ---------------------------------------------------------------------------
__global__ __launch_bounds__(256) void split_hi(
    const float* __restrict__ src, __half* __restrict__ hi, long n4)
{
    for (long i = blockIdx.x * 256 + threadIdx.x; i < n4; i += (long)gridDim.x * 256) {
        float4 v = *reinterpret_cast<const float4*>(src + i * 4);
        __half2 a = __halves2half2(__float2half_rn(v.x), __float2half_rn(v.y));
        __half2 b = __halves2half2(__float2half_rn(v.z), __float2half_rn(v.w));
        uint2 u = make_uint2(*reinterpret_cast<uint32_t*>(&a),
                             *reinterpret_cast<uint32_t*>(&b));
        *reinterpret_cast<uint2*>(hi + i * 4) = u;
    }
}

// ---------------------------------------------------------------------------
// Single-plane GEMM: C = scale * Ah·Bh^T (+ bias).
// EPI: 0 = fp32 C, 1 = GEMM1 epilogue (bias, hi planes out).
// Tiles 128x128, packed 64 phys rows x 128B = 8KB each, 6-stage cp.async.
// ---------------------------------------------------------------------------
template <int EPI>
__global__ __launch_bounds__(256, 2) void mma_gemm(
    const __half* __restrict__ Ah, const __half* __restrict__ Bh,
    const float* __restrict__ bias, float* __restrict__ C,
    __half* __restrict__ qkh, __half* __restrict__ vth,
    int K, int lda, int ldb, int ldc,
    long sA, long sB, long sC, float scale)
{
    extern __shared__ char ds[];
    const int tid  = threadIdx.x;
    const int wid  = tid >> 5;
    const int lane = tid & 31;
    const int bm   = blockIdx.y * 128;
    const int bn   = blockIdx.x * 128;
    const int z    = blockIdx.z;

    Ah += z * sA + (long)bm * lda;
    Bh += z * sB + (long)bn * ldb;

    const int wm = (wid >> 2) << 6;     // 0 or 64
    const int wn = (wid & 3) << 5;      // 0,32,64,96

    float acc[4][4][4];
#pragma unroll
    for (int a = 0; a < 4; a++)
#pragma unroll
        for (int b = 0; b < 4; b++)
#pragma unroll
            for (int c = 0; c < 4; c++) acc[a][b][c] = 0.0f;

    const int nck = K >> 5;
    const uint32_t sb0 = smem_u32(ds);

    auto issue = [&](int ck) {
        const int k0 = ck << 5;
        const uint32_t sbase = sb0 + (ck % STG) * BUFS;
#pragma unroll
        for (int t = 0; t < 2; t++) {
            const int i = tid + t * 256;          // 0..511
            const int r = i >> 2, c = i & 3;
            const __half* src = Ah + (long)r * lda + k0 + c * 8;
            const int pr = r & 63, cc = ((r >> 6) << 2) | c;
            cp_async16(sbase + pr * 128 + ((cc ^ (pr & 7)) << 4), src);
        }
#pragma unroll
        for (int t = 0; t < 2; t++) {
            const int i = tid + t * 256;          // 0..511
            const int r = i >> 2, c = i & 3;
            const __half* src = Bh + (long)r * ldb + k0 + c * 8;
            const int pr = r & 63, cc = ((r >> 6) << 2) | c;
            cp_async16(sbase + OFFB + pr * 128 + ((cc ^ (pr & 7)) << 4), src);
        }
        cp_commit();
    };

#pragma unroll
    for (int i = 0; i < STG - 1; i++) issue(i);

    // ldsm per-lane constants
    const int j = lane >> 3;
    const int arow = ((j & 1) << 3) | (lane & 7);
    const int acnk = j >> 1;
    const int brow = ((j >> 1) << 3) | (lane & 7);
    const int bcnk = j & 1;
    const int r7a = arow & 7;
    const int r7b = brow & 7;
    const int hiA4 = (wm >> 6) << 2;     // A col-block select (0 or 4)

    for (int ck = 0; ck < nck; ck++) {
        cp_wait<STG - 2>();
        __syncthreads();
        if (ck + STG - 1 < nck) issue(ck + STG - 1);

        const uint32_t bfA = sb0 + (ck % STG) * BUFS;
        const uint32_t bfB = bfA + OFFB;
#pragma unroll
        for (int s = 0; s < 2; s++) {
            const int c0 = s * 2;
            uint32_t ah[4][4], bh[2][4];
#pragma unroll
            for (int mt = 0; mt < 4; mt++) {
                const int pr = (mt << 4) + arow;      // 0..63
                const int cc = hiA4 + c0 + acnk;
                ldsm4(ah[mt], bfA + pr * 128 + ((cc ^ r7a) << 4));
            }
#pragma unroll
            for (int nt2 = 0; nt2 < 2; nt2++) {
                const int r = wn + (nt2 << 4) + brow;
                const int pr = r & 63;
                const int cc = ((r >> 6) << 2) + c0 + bcnk;
                ldsm4(bh[nt2], bfB + pr * 128 + ((cc ^ r7b) << 4));
            }
#pragma unroll
            for (int mt = 0; mt < 4; mt++)
#pragma unroll
                for (int nt = 0; nt < 4; nt++) {
                    const int g = nt >> 1, q = (nt & 1) << 1;
                    hmma(acc[mt][nt], ah[mt], bh[g][q], bh[g][q + 1]);
                }
        }
    }

    // ---- epilogue
    const int mrow = lane >> 2;
    const int ncol = (lane & 3) << 1;
    if (EPI == 0) {
        float* Cz = C + (long)z * sC;
#pragma unroll
        for (int mt = 0; mt < 4; mt++) {
            const int m = bm + wm + (mt << 4) + mrow;
#pragma unroll
            for (int nt = 0; nt < 4; nt++) {
                const int n = bn + wn + (nt << 3) + ncol;
                float2 v0 = make_float2(acc[mt][nt][0] * scale, acc[mt][nt][1] * scale);
                float2 v1 = make_float2(acc[mt][nt][2] * scale, acc[mt][nt][3] * scale);
                *reinterpret_cast<float2*>(Cz + (long)m * ldc + n) = v0;
                *reinterpret_cast<float2*>(Cz + (long)(m + 8) * ldc + n) = v1;
            }
        }
    } else {
#pragma unroll
        for (int mt = 0; mt < 4; mt++) {
            const int m0 = bm + wm + (mt << 4) + mrow;
            const int m1 = m0 + 8;
#pragma unroll
            for (int nt = 0; nt < 4; nt++) {
                const int n = bn + wn + (nt << 3) + ncol;
                const float b0 = bias[n], b1 = bias[n + 1];
                __half h00 = __float2half_rn(acc[mt][nt][0] + b0);
                __half h01 = __float2half_rn(acc[mt][nt][1] + b1);
                __half h10 = __float2half_rn(acc[mt][nt][2] + b0);
                __half h11 = __float2half_rn(acc[mt][nt][3] + b1);
                if (n < 2048) {
                    *reinterpret_cast<__half2*>(&qkh[(long)m0 * 2048 + n]) =
                        __halves2half2(h00, h01);
                    *reinterpret_cast<__half2*>(&qkh[(long)m1 * 2048 + n]) =
                        __halves2half2(h10, h11);
                } else {
                    const int d = n - 2048;
                    const int bi0 = m0 >> 11, s0 = m0 & 2047;
                    const int bi1 = m1 >> 11, s1 = m1 & 2047;
                    __half* t0 = vth + (long)bi0 * DIM * SEQ + (long)d * SEQ + s0;
                    __half* t1 = vth + (long)bi1 * DIM * SEQ + (long)d * SEQ + s1;
                    t0[0] = h00; t0[SEQ] = h01;
                    t1[0] = h10; t1[SEQ] = h11;
                }
            }
        }
    }
}

// ---------------------------------------------------------------------------
__global__ __launch_bounds__(256) void softmax_rows_kernel(
    float* __restrict__ w, __half* __restrict__ wph)
{
    float* p = w + (long)blockIdx.x * SEQ;
    const int tid  = threadIdx.x;
    const int lane = tid & 31;
    const int warp = tid >> 5;

    float4 v0 = *reinterpret_cast<const float4*>(&p[tid * 4]);
    float4 v1 = *reinterpret_cast<const float4*>(&p[tid * 4 + 1024]);

    float m = fmaxf(fmaxf(fmaxf(v0.x, v0.y), fmaxf(v0.z, v0.w)),
                    fmaxf(fmaxf(v1.x, v1.y), fmaxf(v1.z, v1.w)));
    __shared__ float red[8];
#pragma unroll
    for (int o = 16; o; o >>= 1) m = fmaxf(m, __shfl_xor_sync(0xffffffffu, m, o));
    if (lane == 0) red[warp] = m;
    __syncthreads();
    float rmax = red[0];
#pragma unroll
    for (int i = 1; i < 8; i++) rmax = fmaxf(rmax, red[i]);
    __syncthreads();

    v0.x = __expf(v0.x - rmax); v0.y = __expf(v0.y - rmax);
    v0.z = __expf(v0.z - rmax); v0.w = __expf(v0.w - rmax);
    v1.x = __expf(v1.x - rmax); v1.y = __expf(v1.y - rmax);
    v1.z = __expf(v1.z - rmax); v1.w = __expf(v1.w - rmax);
    float s = v0.x + v0.y + v0.z + v0.w + v1.x + v1.y + v1.z + v1.w;
#pragma unroll
    for (int o = 16; o; o >>= 1) s += __shfl_xor_sync(0xffffffffu, s, o);
    if (lane == 0) red[warp] = s;
    __syncthreads();
    float tot = 0.0f;
#pragma unroll
    for (int i = 0; i < 8; i++) tot += red[i];
    const float inv = 1.0f / tot;

    v0.x *= inv; v0.y *= inv; v0.z *= inv; v0.w *= inv;
    v1.x *= inv; v1.y *= inv; v1.z *= inv; v1.w *= inv;
    *reinterpret_cast<float4*>(&p[tid * 4])        = v0;
    *reinterpret_cast<float4*>(&p[tid * 4 + 1024]) = v1;

    __half* ph = wph + (long)blockIdx.x * SEQ;
#pragma unroll
    for (int half = 0; half < 2; half++) {
        float4 v = half ? v1 : v0;
        const int off = tid * 4 + half * 1024;
        __half2 a = __halves2half2(__float2half_rn(v.x), __float2half_rn(v.y));
        __half2 b = __halves2half2(__float2half_rn(v.z), __float2half_rn(v.w));
        uint2 u = make_uint2(*reinterpret_cast<uint32_t*>(&a),
                             *reinterpret_cast<uint32_t*>(&b));
        *reinterpret_cast<uint2*>(ph + off) = u;
    }
}

// ---------------------------------------------------------------------------
extern "C" void kernel_launch(void* const* d_in, const int* in_sizes, int n_in,
                              void* d_out, int out_size)
{
    const float* x  = (const float*)d_in[0];
    const float* Wq = (const float*)d_in[1];
    const float* bq = (const float*)d_in[2];

    float* out_attn = (float*)d_out;
    float* out_w    = out_attn + (long)ROWS * DIM;

    __half *xh, *wh, *qkh, *vth, *wph;
    cudaGetSymbolAddress((void**)&xh, g_xh);
    cudaGetSymbolAddress((void**)&wh, g_wh);
    cudaGetSymbolAddress((void**)&qkh, g_qkh);
    cudaGetSymbolAddress((void**)&vth, g_vth);
    cudaGetSymbolAddress((void**)&wph, g_wph);

    const int SMEM = STG * BUFS;    // 98304
    cudaFuncSetAttribute(mma_gemm<0>,
                         cudaFuncAttributeMaxDynamicSharedMemorySize, SMEM);
    cudaFuncSetAttribute(mma_gemm<1>,
                         cudaFuncAttributeMaxDynamicSharedMemorySize, SMEM);

    // 0) prepass: x, W -> fp16 hi planes
    split_hi<<<592, 256>>>(x, xh, (long)ROWS * DIM / 4);
    split_hi<<<296, 256>>>(Wq, wh, (long)3 * DIM * DIM / 4);

    // 1) qkv = xh @ Wh^T + b -> Q|K hi plane + V^T hi plane
    mma_gemm<1><<<dim3(24, 64, 1), 256, SMEM>>>(
        xh, wh, bq, nullptr,
        qkh, vth,
        1024, 1024, 1024, 0, 0, 0, 0, 1.0f);

    // 2) scores = Qh @ Kh^T / 32 -> fp32 w region
    mma_gemm<0><<<dim3(16, 16, BATCH), 256, SMEM>>>(
        qkh, qkh + 1024, nullptr, out_w,
        nullptr, nullptr,
        1024, 2048, 2048, 2048,
        (long)SEQ * 2048, (long)SEQ * 2048, (long)SEQ * SEQ, 1.0f / 32.0f);

    // 3) softmax rows in place + emit w hi plane
    softmax_rows_kernel<<<ROWS, 256>>>(out_w, wph);

    // 4) out = wh @ Vh^T : M=2048, N=1024, K=2048, batched
    mma_gemm<0><<<dim3(8, 16, BATCH), 256, SMEM>>>(
        wph, vth, nullptr, out_attn,
        nullptr, nullptr,
        2048, 2048, 2048, 1024,
        (long)SEQ * SEQ, (long)DIM * SEQ, (long)SEQ * DIM, 1.0f);
}

// round 11
// speedup vs baseline: 7.7567x; 1.0397x over previous
#include <cuda_runtime.h>
#include <cuda_fp16.h>
#include <cstdint>

// ---------------------------------------------------------------------------
// MaskedAttention via single-plane fp16 mma.sync GEMMs, K=64 stages.
// GEMM1: qkv = xh·Wh+b -> Qh/Kh planes + Vh^T plane.
// GEMM2: scores = Qh·Kh/32 -> fp32 w. softmax -> w fp32 + wh plane.
// GEMM4: out = wh·Vh.   All NT: C[m,n]=scale*sum_k A[m,k]B[n,k].
// ---------------------------------------------------------------------------

#define BATCH 4
#define SEQ   2048
#define DIM   1024
#define ROWS  (BATCH * SEQ)      // 8192

__device__ __half g_xh[(long)ROWS * DIM];
__device__ __half g_wh[(long)3 * DIM * DIM];
__device__ __half g_qkh[(long)ROWS * 2048];           // Q|K hi plane
__device__ __half g_vth[(long)BATCH * DIM * SEQ];     // V^T hi plane
__device__ __half g_wph[(long)ROWS * SEQ];            // softmax(w) hi plane

#define NSTAGE 3
#define STAGEB 32768       // [A0 8K][B0 8K][A1 8K][B1 8K]
#define SMEM_TOTAL (NSTAGE * STAGEB)

__device__ __forceinline__ uint32_t smem_u32(const void* p) {
    uint32_t a;
    asm("{ .reg .u64 t; cvta.to.shared.u64 t, %1; cvt.u32.u64 %0, t; }"
        : "=r"(a) : "l"(p));
    return a;
}
__device__ __forceinline__ void cp_async16(uint32_t s, const void* g) {
    asm volatile("cp.async.cg.shared.global [%0], [%1], 16;" :: "r"(s), "l"(g));
}
__device__ __forceinline__ void cp_commit() {
    asm volatile("cp.async.commit_group;" ::: "memory");
}
template <int N>
__device__ __forceinline__ void cp_wait() {
    asm volatile("cp.async.wait_group %0;" :: "n"(N) : "memory");
}
__device__ __forceinline__ void ldsm4(uint32_t* r, uint32_t addr) {
    asm volatile("ldmatrix.sync.aligned.m8n8.x4.shared.b16 {%0,%1,%2,%3}, [%4];"
                 : "=r"(r[0]), "=r"(r[1]), "=r"(r[2]), "=r"(r[3]) : "r"(addr));
}
__device__ __forceinline__ void hmma(float* c, const uint32_t* a, uint32_t b0, uint32_t b1) {
    asm volatile(
        "mma.sync.aligned.m16n8k16.row.col.f32.f16.f16.f32 "
        "{%0,%1,%2,%3}, {%4,%5,%6,%7}, {%8,%9}, {%0,%1,%2,%3};"
        : "+f"(c[0]), "+f"(c[1]), "+f"(c[2]), "+f"(c[3])
        : "r"(a[0]), "r"(a[1]), "r"(a[2]), "r"(a[3]), "r"(b0), "r"(b1));
}

// ---------------------------------------------------------------------------
__global__ __launch_bounds__(256) void split_hi(
    const float* __restrict__ src, __half* __restrict__ hi, long n4)
{
    for (long i = blockIdx.x * 256 + threadIdx.x; i < n4; i += (long)gridDim.x * 256) {
        float4 v = *reinterpret_cast<const float4*>(src + i * 4);
        __half2 a = __halves2half2(__float2half_rn(v.x), __float2half_rn(v.y));
        __half2 b = __halves2half2(__float2half_rn(v.z), __float2half_rn(v.w));
        uint2 u = make_uint2(*reinterpret_cast<uint32_t*>(&a),
                             *reinterpret_cast<uint32_t*>(&b));
        *reinterpret_cast<uint2*>(hi + i * 4) = u;
    }
}

// ---------------------------------------------------------------------------
// Single-plane GEMM: C = scale * Ah·Bh^T (+ bias).
// EPI: 0 = fp32 C, 1 = GEMM1 epilogue (bias, hi planes out).
// 128x128 CTA tile; K=64 per stage; 3 stages; one barrier per stage.
// ---------------------------------------------------------------------------
template <int EPI>
__global__ __launch_bounds__(256, 2) void mma_gemm(
    const __half* __restrict__ Ah, const __half* __restrict__ Bh,
    const float* __restrict__ bias, float* __restrict__ C,
    __half* __restrict__ qkh, __half* __restrict__ vth,
    int K, int lda, int ldb, int ldc,
    long sA, long sB, long sC, float scale)
{
    extern __shared__ char ds[];
    const int tid  = threadIdx.x;
    const int wid  = tid >> 5;
    const int lane = tid & 31;
    const int bm   = blockIdx.y * 128;
    const int bn   = blockIdx.x * 128;
    const int z    = blockIdx.z;

    Ah += z * sA + (long)bm * lda;
    Bh += z * sB + (long)bn * ldb;

    const int wm = (wid >> 2) << 6;     // 0 or 64
    const int wn = (wid & 3) << 5;      // 0,32,64,96

    float acc[4][4][4];
#pragma unroll
    for (int a = 0; a < 4; a++)
#pragma unroll
        for (int b = 0; b < 4; b++)
#pragma unroll
            for (int c = 0; c < 4; c++) acc[a][b][c] = 0.0f;

    const int nst = K >> 6;             // K64 stages
    const uint32_t sb0 = smem_u32(ds);

    // issue one K=64 stage (two k32 sub-chunks), single commit
    auto issue_stage = [&](int st) {
        const uint32_t stbase = sb0 + (st % NSTAGE) * STAGEB;
#pragma unroll
        for (int sub = 0; sub < 2; sub++) {
            const int k0 = (st << 6) + (sub << 5);
            const uint32_t sbase = stbase + sub * 16384;
#pragma unroll
            for (int t = 0; t < 2; t++) {
                const int i = tid + t * 256;          // 0..511
                const int r = i >> 2, c = i & 3;
                const __half* src = Ah + (long)r * lda + k0 + c * 8;
                const int pr = r & 63, cc = ((r >> 6) << 2) | c;
                cp_async16(sbase + pr * 128 + ((cc ^ (pr & 7)) << 4), src);
            }
#pragma unroll
            for (int t = 0; t < 2; t++) {
                const int i = tid + t * 256;          // 0..511
                const int r = i >> 2, c = i & 3;
                const __half* src = Bh + (long)r * ldb + k0 + c * 8;
                const int pr = r & 63, cc = ((r >> 6) << 2) | c;
                cp_async16(sbase + 8192 + pr * 128 + ((cc ^ (pr & 7)) << 4), src);
            }
        }
        cp_commit();
    };

    issue_stage(0);
    if (nst > 1) issue_stage(1);

    // ldsm per-lane constants
    const int j = lane >> 3;
    const int arow = ((j & 1) << 3) | (lane & 7);
    const int acnk = j >> 1;
    const int brow = ((j >> 1) << 3) | (lane & 7);
    const int bcnk = j & 1;
    const int r7a = arow & 7;
    const int r7b = brow & 7;
    const int hiA4 = (wm >> 6) << 2;     // A col-block select (0 or 4)

    for (int st = 0; st < nst; st++) {
        cp_wait<1>();
        __syncthreads();
        if (st + 2 < nst) issue_stage(st + 2);

        const uint32_t stbase = sb0 + (st % NSTAGE) * STAGEB;
#pragma unroll
        for (int sub = 0; sub < 2; sub++) {
            const uint32_t bfA = stbase + sub * 16384;
            const uint32_t bfB = bfA + 8192;
#pragma unroll
            for (int s = 0; s < 2; s++) {
                const int c0 = s * 2;
                uint32_t ah[4][4], bh[2][4];
#pragma unroll
                for (int mt = 0; mt < 4; mt++) {
                    const int pr = (mt << 4) + arow;      // 0..63
                    const int cc = hiA4 + c0 + acnk;
                    ldsm4(ah[mt], bfA + pr * 128 + ((cc ^ r7a) << 4));
                }
#pragma unroll
                for (int nt2 = 0; nt2 < 2; nt2++) {
                    const int r = wn + (nt2 << 4) + brow;
                    const int pr = r & 63;
                    const int cc = ((r >> 6) << 2) + c0 + bcnk;
                    ldsm4(bh[nt2], bfB + pr * 128 + ((cc ^ r7b) << 4));
                }
#pragma unroll
                for (int mt = 0; mt < 4; mt++)
#pragma unroll
                    for (int nt = 0; nt < 4; nt++) {
                        const int g = nt >> 1, q = (nt & 1) << 1;
                        hmma(acc[mt][nt], ah[mt], bh[g][q], bh[g][q + 1]);
                    }
            }
        }
    }

    // ---- epilogue
    const int mrow = lane >> 2;
    const int ncol = (lane & 3) << 1;
    if (EPI == 0) {
        float* Cz = C + (long)z * sC;
#pragma unroll
        for (int mt = 0; mt < 4; mt++) {
            const int m = bm + wm + (mt << 4) + mrow;
#pragma unroll
            for (int nt = 0; nt < 4; nt++) {
                const int n = bn + wn + (nt << 3) + ncol;
                float2 v0 = make_float2(acc[mt][nt][0] * scale, acc[mt][nt][1] * scale);
                float2 v1 = make_float2(acc[mt][nt][2] * scale, acc[mt][nt][3] * scale);
                *reinterpret_cast<float2*>(Cz + (long)m * ldc + n) = v0;
                *reinterpret_cast<float2*>(Cz + (long)(m + 8) * ldc + n) = v1;
            }
        }
    } else {
#pragma unroll
        for (int mt = 0; mt < 4; mt++) {
            const int m0 = bm + wm + (mt << 4) + mrow;
            const int m1 = m0 + 8;
#pragma unroll
            for (int nt = 0; nt < 4; nt++) {
                const int n = bn + wn + (nt << 3) + ncol;
                const float b0 = bias[n], b1 = bias[n + 1];
                __half h00 = __float2half_rn(acc[mt][nt][0] + b0);
                __half h01 = __float2half_rn(acc[mt][nt][1] + b1);
                __half h10 = __float2half_rn(acc[mt][nt][2] + b0);
                __half h11 = __float2half_rn(acc[mt][nt][3] + b1);
                if (n < 2048) {
                    *reinterpret_cast<__half2*>(&qkh[(long)m0 * 2048 + n]) =
                        __halves2half2(h00, h01);
                    *reinterpret_cast<__half2*>(&qkh[(long)m1 * 2048 + n]) =
                        __halves2half2(h10, h11);
                } else {
                    const int d = n - 2048;
                    const int bi0 = m0 >> 11, s0 = m0 & 2047;
                    const int bi1 = m1 >> 11, s1 = m1 & 2047;
                    __half* t0 = vth + (long)bi0 * DIM * SEQ + (long)d * SEQ + s0;
                    __half* t1 = vth + (long)bi1 * DIM * SEQ + (long)d * SEQ + s1;
                    t0[0] = h00; t0[SEQ] = h01;
                    t1[0] = h10; t1[SEQ] = h11;
                }
            }
        }
    }
}

// ---------------------------------------------------------------------------
__global__ __launch_bounds__(256) void softmax_rows_kernel(
    float* __restrict__ w, __half* __restrict__ wph)
{
    float* p = w + (long)blockIdx.x * SEQ;
    const int tid  = threadIdx.x;
    const int lane = tid & 31;
    const int warp = tid >> 5;

    float4 v0 = *reinterpret_cast<const float4*>(&p[tid * 4]);
    float4 v1 = *reinterpret_cast<const float4*>(&p[tid * 4 + 1024]);

    float m = fmaxf(fmaxf(fmaxf(v0.x, v0.y), fmaxf(v0.z, v0.w)),
                    fmaxf(fmaxf(v1.x, v1.y), fmaxf(v1.z, v1.w)));
    __shared__ float red[8];
#pragma unroll
    for (int o = 16; o; o >>= 1) m = fmaxf(m, __shfl_xor_sync(0xffffffffu, m, o));
    if (lane == 0) red[warp] = m;
    __syncthreads();
    float rmax = red[0];
#pragma unroll
    for (int i = 1; i < 8; i++) rmax = fmaxf(rmax, red[i]);
    __syncthreads();

    v0.x = __expf(v0.x - rmax); v0.y = __expf(v0.y - rmax);
    v0.z = __expf(v0.z - rmax); v0.w = __expf(v0.w - rmax);
    v1.x = __expf(v1.x - rmax); v1.y = __expf(v1.y - rmax);
    v1.z = __expf(v1.z - rmax); v1.w = __expf(v1.w - rmax);
    float s = v0.x + v0.y + v0.z + v0.w + v1.x + v1.y + v1.z + v1.w;
#pragma unroll
    for (int o = 16; o; o >>= 1) s += __shfl_xor_sync(0xffffffffu, s, o);
    if (lane == 0) red[warp] = s;
    __syncthreads();
    float tot = 0.0f;
#pragma unroll
    for (int i = 0; i < 8; i++) tot += red[i];
    const float inv = 1.0f / tot;

    v0.x *= inv; v0.y *= inv; v0.z *= inv; v0.w *= inv;
    v1.x *= inv; v1.y *= inv; v1.z *= inv; v1.w *= inv;
    *reinterpret_cast<float4*>(&p[tid * 4])        = v0;
    *reinterpret_cast<float4*>(&p[tid * 4 + 1024]) = v1;

    __half* ph = wph + (long)blockIdx.x * SEQ;
#pragma unroll
    for (int half = 0; half < 2; half++) {
        float4 v = half ? v1 : v0;
        const int off = tid * 4 + half * 1024;
        __half2 a = __halves2half2(__float2half_rn(v.x), __float2half_rn(v.y));
        __half2 b = __halves2half2(__float2half_rn(v.z), __float2half_rn(v.w));
        uint2 u = make_uint2(*reinterpret_cast<uint32_t*>(&a),
                             *reinterpret_cast<uint32_t*>(&b));
        *reinterpret_cast<uint2*>(ph + off) = u;
    }
}

// ---------------------------------------------------------------------------
extern "C" void kernel_launch(void* const* d_in, const int* in_sizes, int n_in,
                              void* d_out, int out_size)
{
    const float* x  = (const float*)d_in[0];
    const float* Wq = (const float*)d_in[1];
    const float* bq = (const float*)d_in[2];

    float* out_attn = (float*)d_out;
    float* out_w    = out_attn + (long)ROWS * DIM;

    __half *xh, *wh, *qkh, *vth, *wph;
    cudaGetSymbolAddress((void**)&xh, g_xh);
    cudaGetSymbolAddress((void**)&wh, g_wh);
    cudaGetSymbolAddress((void**)&qkh, g_qkh);
    cudaGetSymbolAddress((void**)&vth, g_vth);
    cudaGetSymbolAddress((void**)&wph, g_wph);

    cudaFuncSetAttribute(mma_gemm<0>,
                         cudaFuncAttributeMaxDynamicSharedMemorySize, SMEM_TOTAL);
    cudaFuncSetAttribute(mma_gemm<1>,
                         cudaFuncAttributeMaxDynamicSharedMemorySize, SMEM_TOTAL);

    // 0) prepass: x, W -> fp16 hi planes
    split_hi<<<592, 256>>>(x, xh, (long)ROWS * DIM / 4);
    split_hi<<<296, 256>>>(Wq, wh, (long)3 * DIM * DIM / 4);

    // 1) qkv = xh @ Wh^T + b -> Q|K hi plane + V^T hi plane
    mma_gemm<1><<<dim3(24, 64, 1), 256, SMEM_TOTAL>>>(
        xh, wh, bq, nullptr,
        qkh, vth,
        1024, 1024, 1024, 0, 0, 0, 0, 1.0f);

    // 2) scores = Qh @ Kh^T / 32 -> fp32 w region
    mma_gemm<0><<<dim3(16, 16, BATCH), 256, SMEM_TOTAL>>>(
        qkh, qkh + 1024, nullptr, out_w,
        nullptr, nullptr,
        1024, 2048, 2048, 2048,
        (long)SEQ * 2048, (long)SEQ * 2048, (long)SEQ * SEQ, 1.0f / 32.0f);

    // 3) softmax rows in place + emit w hi plane
    softmax_rows_kernel<<<ROWS, 256>>>(out_w, wph);

    // 4) out = wh @ Vh^T : M=2048, N=1024, K=2048, batched
    mma_gemm<0><<<dim3(8, 16, BATCH), 256, SMEM_TOTAL>>>(
        wph, vth, nullptr, out_attn,
        nullptr, nullptr,
        2048, 2048, 2048, 1024,
        (long)SEQ * SEQ, (long)DIM * SEQ, (long)SEQ * DIM, 1.0f);
}